// round 6
// baseline (speedup 1.0000x reference)
#include <cuda_runtime.h>
#include <cuda_bf16.h>
#include <math.h>

#define MTOK   73728
#define CDIM   192
#define NHEAD  6
#define HD     32
#define NTOK   144
#define NWIN   512
#define TWIN   32
#define NWW    16
#define NB     3312
#define QKVN   576
#define FFN    768

__device__ float g_x  [(size_t)MTOK * CDIM];
__device__ float g_qkv[(size_t)MTOK * QKVN];
__device__ float g_ao [(size_t)MTOK * CDIM];
__device__ float g_tmp[(size_t)MTOK * CDIM];
__device__ float g_h  [(size_t)MTOK * FFN];
__device__ float g_bm [(size_t)2 * TWIN * NHEAD * NTOK * NTOK];
// tf32-pre-rounded weights: qkv | proj | w1 | w2  (both layers)
#define WQ_OFF 0
#define WP_OFF 221184
#define W1_OFF 294912
#define W2_OFF 589824
__device__ float g_wt [884736];

// ---------------------------------------------------------------------------
// helpers
// ---------------------------------------------------------------------------
__device__ __forceinline__ unsigned f2tf32(float x) {
    unsigned r;
    asm("cvt.rna.tf32.f32 %0, %1;" : "=r"(r) : "f"(x));
    return r;
}
__device__ __forceinline__ float f2tf32f(float x) { return __uint_as_float(f2tf32(x)); }

__device__ __forceinline__ void mma_tf32(float* d, const unsigned* a, const unsigned* b) {
    asm volatile(
        "mma.sync.aligned.m16n8k8.row.col.f32.tf32.tf32.f32 "
        "{%0,%1,%2,%3}, {%4,%5,%6,%7}, {%8,%9}, {%0,%1,%2,%3};\n"
        : "+f"(d[0]), "+f"(d[1]), "+f"(d[2]), "+f"(d[3])
        : "r"(a[0]), "r"(a[1]), "r"(a[2]), "r"(a[3]),
          "r"(b[0]), "r"(b[1]));
}

__device__ __forceinline__ unsigned smaddr(const void* p) {
    return (unsigned)__cvta_generic_to_shared(p);
}
#define CPA16(dst, src) asm volatile("cp.async.cg.shared.global [%0], [%1], 16;" :: "r"(dst), "l"(src))
#define CPCOMMIT()      asm volatile("cp.async.commit_group;")
#define CPWAIT1()       asm volatile("cp.async.wait_group 1;")

__device__ __forceinline__ float gelu_exact(float v) {
    return 0.5f * v * (1.0f + erff(v * 0.70710678118654752f));
}

__global__ void round_weights_kernel(const float* __restrict__ src,
                                     float* __restrict__ dst, int n) {
    int i = blockIdx.x * blockDim.x + threadIdx.x;
    if (i < n) dst[i] = f2tf32f(src[i]);
}

// ---------------------------------------------------------------------------
// Dense (relative-position bias + shift mask)
// ---------------------------------------------------------------------------
__global__ void biasmask_kernel(const float* __restrict__ table) {
    size_t idx = (size_t)blockIdx.x * blockDim.x + threadIdx.x;
    size_t total = (size_t)2 * TWIN * NHEAD * NTOK * NTOK;
    if (idx >= total) return;
    int m = idx % NTOK; size_t r = idx / NTOK;
    int n = r % NTOK;   r /= NTOK;
    int head = r % NHEAD; r /= NHEAD;
    int t = r % TWIN;   int L = (int)(r / TWIN);
    int z1 = n / 72, h1 = (n % 72) / 12, w1 = n % 12;
    int z2 = m / 72, h2 = (m % 72) / 12, w2 = m % 12;
    int pos = 828 * (z1 + 2 * z2) + 23 * (h1 + 6 * h2) + (w1 - w2 + 11);
    float v = table[(((size_t)L * NB + pos) * TWIN + t) * NHEAD + head];
    if (L == 1) {
        int tz = t / 8, th = t % 8;
        int idn = (((tz * 2 + z1) >= 1) ? 2 : 0) + (((th * 6 + h1) >= 3) ? 1 : 0);
        int idm = (((tz * 2 + z2) >= 1) ? 2 : 0) + (((th * 6 + h2) >= 3) ? 1 : 0);
        if (idn != idm) v += -10000.0f;
    }
    g_bm[idx] = v;
}

// ---------------------------------------------------------------------------
// tf32 GEMM: BM=128, BN=64, BK=32, 128 threads / 4 warps (2x2),
// warp tile 64x32 (mt=4, nt=4) -> 16 mma per ks-step, 1.5 LDS/mma.
// 2-stage cp.async pipeline. B pre-rounded to tf32 (raw-bit fragments).
// ACVT: A fragments need cvt (fp32 A). ROUND: round outputs to tf32.
// GATHER: A rows window-remapped; `rolled` selects shifted mapping.
// ---------------------------------------------------------------------------
#define ASTG (128 * 36)
#define BSTG (32 * 72)
#define GEMM_SMEM ((2 * ASTG + 2 * BSTG) * 4)   // 55296 B

template <int EPI, int GATHER, int ACVT, int ROUND>
__global__ void __launch_bounds__(128, 4)
mma_gemm_kernel(const float* __restrict__ A,
                const float* __restrict__ B,
                const float* __restrict__ bias,
                float* __restrict__ Cm,
                int K, int Nn, int rolled) {
    extern __shared__ float dsm[];
    float* As = dsm;
    float* Bs = dsm + 2 * ASTG;

    const int tid  = threadIdx.x;
    const int lane = tid & 31;
    const int wid  = tid >> 5;
    const int wm   = wid >> 1;          // 0..1 (64 rows each)
    const int wn   = wid & 1;           // 0..1 (32 cols each)
    const int g    = lane >> 2;
    const int tg   = lane & 3;
    const int m0   = blockIdx.y * 128;
    const int n0   = blockIdx.x * 64;

    // copy roles: A -> thread = row (8 x f4); B -> 4 threads/row (4 x f4)
    const int brow = tid >> 2;
    const int bf40 = tid & 3;

    size_t arowp;
    {
        int r = m0 + tid;
        if (GATHER) {
            int n = r % NTOK, win = r / NTOK;
            int l = win % NWW, t = win / NWW;
            int tz = t / 8, th = t % 8;
            int z1 = n / 72, h1 = (n % 72) / 12, w1 = n % 12;
            int zr = tz * 2 + z1, hr = th * 6 + h1, wr = l * 12 + w1;
            int z, hh, ww;
            if (rolled) { z = (zr + 7) & 7; hh = (hr + 45) % 48; ww = (wr + 186) % 192; }
            else        { z = zr; hh = hr; ww = wr; }
            arowp = ((size_t)z * 48 + hh) * 192 + ww;
        } else {
            arowp = (size_t)r;
        }
    }
    const float* aSrc = A + arowp * K;
    const float* bSrc = B + (size_t)brow * Nn + n0 + bf40 * 4;

    float acc[4][4][4];
    #pragma unroll
    for (int mt = 0; mt < 4; mt++)
        #pragma unroll
        for (int nt = 0; nt < 4; nt++)
            #pragma unroll
            for (int i = 0; i < 4; i++) acc[mt][nt][i] = 0.0f;

    // prologue: stages 0,1
    #pragma unroll
    for (int s = 0; s < 2; s++) {
        float* as = As + s * ASTG;
        float* bs = Bs + s * BSTG;
        const int k0 = s * 32;
        #pragma unroll
        for (int i = 0; i < 8; i++)
            CPA16(smaddr(as + tid * 36 + i * 4), aSrc + k0 + i * 4);
        #pragma unroll
        for (int i = 0; i < 4; i++)
            CPA16(smaddr(bs + brow * 72 + (bf40 + 4 * i) * 4),
                  bSrc + (size_t)k0 * Nn + 16 * i);
        CPCOMMIT();
    }

    const int iters = K >> 5;
    for (int it = 0; it < iters; it++) {
        const int cur = it & 1;
        CPWAIT1();
        __syncthreads();

        const float* as = As + cur * ASTG;
        const float* bs = Bs + cur * BSTG;
        #pragma unroll
        for (int ks = 0; ks < 4; ks++) {
            const int kk = ks * 8;
            unsigned af[4][4], bf[4][2];
            #pragma unroll
            for (int mt = 0; mt < 4; mt++) {
                int rbse = wm * 64 + mt * 16;
                if (ACVT) {
                    af[mt][0] = f2tf32(as[(rbse + g)     * 36 + kk + tg]);
                    af[mt][1] = f2tf32(as[(rbse + 8 + g) * 36 + kk + tg]);
                    af[mt][2] = f2tf32(as[(rbse + g)     * 36 + kk + tg + 4]);
                    af[mt][3] = f2tf32(as[(rbse + 8 + g) * 36 + kk + tg + 4]);
                } else {
                    af[mt][0] = __float_as_uint(as[(rbse + g)     * 36 + kk + tg]);
                    af[mt][1] = __float_as_uint(as[(rbse + 8 + g) * 36 + kk + tg]);
                    af[mt][2] = __float_as_uint(as[(rbse + g)     * 36 + kk + tg + 4]);
                    af[mt][3] = __float_as_uint(as[(rbse + 8 + g) * 36 + kk + tg + 4]);
                }
            }
            #pragma unroll
            for (int nt = 0; nt < 4; nt++) {
                int cb = wn * 32 + nt * 8;
                bf[nt][0] = __float_as_uint(bs[(kk + tg)     * 72 + cb + g]);
                bf[nt][1] = __float_as_uint(bs[(kk + 4 + tg) * 72 + cb + g]);
            }
            #pragma unroll
            for (int mt = 0; mt < 4; mt++)
                #pragma unroll
                for (int nt = 0; nt < 4; nt++)
                    mma_tf32(acc[mt][nt], af[mt], bf[nt]);
        }
        __syncthreads();

        const int k0n = (it + 2) << 5;
        if (k0n < K) {
            float* asw = As + cur * ASTG;
            float* bsw = Bs + cur * BSTG;
            #pragma unroll
            for (int i = 0; i < 8; i++)
                CPA16(smaddr(asw + tid * 36 + i * 4), aSrc + k0n + i * 4);
            #pragma unroll
            for (int i = 0; i < 4; i++)
                CPA16(smaddr(bsw + brow * 72 + (bf40 + 4 * i) * 4),
                      bSrc + (size_t)k0n * Nn + 16 * i);
        }
        CPCOMMIT();
    }

    #pragma unroll
    for (int mt = 0; mt < 4; mt++) {
        int r0 = m0 + wm * 64 + mt * 16 + g;
        #pragma unroll
        for (int nt = 0; nt < 4; nt++) {
            int c = n0 + wn * 32 + nt * 8 + tg * 2;
            float b0 = bias[c], b1 = bias[c + 1];
            float v0 = acc[mt][nt][0] + b0;
            float v1 = acc[mt][nt][1] + b1;
            float v2 = acc[mt][nt][2] + b0;
            float v3 = acc[mt][nt][3] + b1;
            if (EPI == 1) {
                v0 = gelu_exact(v0); v1 = gelu_exact(v1);
                v2 = gelu_exact(v2); v3 = gelu_exact(v3);
            }
            if (ROUND) {
                v0 = f2tf32f(v0); v1 = f2tf32f(v1);
                v2 = f2tf32f(v2); v3 = f2tf32f(v3);
            }
            *reinterpret_cast<float2*>(Cm + (size_t)r0 * Nn + c)       = make_float2(v0, v1);
            *reinterpret_cast<float2*>(Cm + (size_t)(r0 + 8) * Nn + c) = make_float2(v2, v3);
        }
    }
}

// ---------------------------------------------------------------------------
// Tensor-core window attention. qkv arrives pre-rounded to tf32 -> zero cvts
// on q/k/v. 1/sqrt(32) scale folded into the bias fmaf after the S-mma.
// Output rounded to tf32 (proj GEMM consumes raw bits).
// ---------------------------------------------------------------------------
#define KS_S  36
#define VS_S  40
#define SCR_S 76
#define ATTN_SMEM ((NTOK * KS_S + NTOK * VS_S + 4 * 16 * SCR_S) * 4)

__global__ void __launch_bounds__(128, 3) attn_mma_kernel(int L) {
    const int win  = blockIdx.x;
    const int head = blockIdx.y;
    const int t    = win >> 4;
    extern __shared__ float sm[];
    float* ks  = sm;                        // [144][36]
    float* vs  = ks + NTOK * KS_S;          // [144][40]
    float* scr = vs + NTOK * VS_S;          // 4 x [16][76]

    const int tid  = threadIdx.x;
    const int lane = tid & 31;
    const int wid  = tid >> 5;
    const int g    = lane >> 2;
    const int tg   = lane & 3;

    const float* base = g_qkv + (size_t)win * NTOK * QKVN;
    const int hc4 = head * 8;
    for (int idx = tid; idx < NTOK * 8; idx += 128) {
        int row = idx >> 3, j = idx & 7;
        const float4* rp = reinterpret_cast<const float4*>(base + (size_t)row * QKVN);
        *reinterpret_cast<float4*>(&ks[row * KS_S + j * 4]) = rp[48 + hc4 + j];
        *reinterpret_cast<float4*>(&vs[row * VS_S + j * 4]) = rp[96 + hc4 + j];
    }
    __syncthreads();

    const float* bmb = g_bm + (((size_t)L * TWIN + t) * NHEAD + head) * NTOK * NTOK;
    float* wscr = scr + wid * 16 * SCR_S;
    const float sc = 0.17677669529663687f;   // 1/sqrt(32)

    for (int mt = wid; mt < 9; mt += 4) {
        const int rb = mt * 16;

        const float* qA = g_qkv + (size_t)(win * NTOK + rb + g) * QKVN + head * HD;
        const float* qB = g_qkv + (size_t)(win * NTOK + rb + 8 + g) * QKVN + head * HD;
        unsigned aq[4][4];
        #pragma unroll
        for (int kk4 = 0; kk4 < 4; kk4++) {
            const int kc = kk4 * 8;
            aq[kk4][0] = __float_as_uint(qA[kc + tg]);
            aq[kk4][1] = __float_as_uint(qB[kc + tg]);
            aq[kk4][2] = __float_as_uint(qA[kc + tg + 4]);
            aq[kk4][3] = __float_as_uint(qB[kc + tg + 4]);
        }

        float sacc[18][4];
        #pragma unroll
        for (int nt = 0; nt < 18; nt++) {
            sacc[nt][0] = sacc[nt][1] = sacc[nt][2] = sacc[nt][3] = 0.0f;
            const int cb = nt * 8;
            #pragma unroll
            for (int kk4 = 0; kk4 < 4; kk4++) {
                const int kc = kk4 * 8;
                unsigned bf[2];
                bf[0] = __float_as_uint(ks[(cb + g) * KS_S + kc + tg]);
                bf[1] = __float_as_uint(ks[(cb + g) * KS_S + kc + tg + 4]);
                mma_tf32(sacc[nt], aq[kk4], bf);
            }
            const float2 bA = *reinterpret_cast<const float2*>(
                bmb + (size_t)(rb + g) * NTOK + cb + tg * 2);
            const float2 bB = *reinterpret_cast<const float2*>(
                bmb + (size_t)(rb + 8 + g) * NTOK + cb + tg * 2);
            sacc[nt][0] = fmaf(sacc[nt][0], sc, bA.x);
            sacc[nt][1] = fmaf(sacc[nt][1], sc, bA.y);
            sacc[nt][2] = fmaf(sacc[nt][2], sc, bB.x);
            sacc[nt][3] = fmaf(sacc[nt][3], sc, bB.y);
        }

        float mxA = -1e30f, mxB = -1e30f;
        #pragma unroll
        for (int nt = 0; nt < 18; nt++) {
            mxA = fmaxf(mxA, fmaxf(sacc[nt][0], sacc[nt][1]));
            mxB = fmaxf(mxB, fmaxf(sacc[nt][2], sacc[nt][3]));
        }
        #pragma unroll
        for (int o = 1; o <= 2; o <<= 1) {
            mxA = fmaxf(mxA, __shfl_xor_sync(0xFFFFFFFFu, mxA, o));
            mxB = fmaxf(mxB, __shfl_xor_sync(0xFFFFFFFFu, mxB, o));
        }
        float smA = 0.0f, smB = 0.0f;
        #pragma unroll
        for (int nt = 0; nt < 18; nt++) {
            sacc[nt][0] = __expf(sacc[nt][0] - mxA);
            sacc[nt][1] = __expf(sacc[nt][1] - mxA);
            sacc[nt][2] = __expf(sacc[nt][2] - mxB);
            sacc[nt][3] = __expf(sacc[nt][3] - mxB);
            smA += sacc[nt][0] + sacc[nt][1];
            smB += sacc[nt][2] + sacc[nt][3];
        }
        #pragma unroll
        for (int o = 1; o <= 2; o <<= 1) {
            smA += __shfl_xor_sync(0xFFFFFFFFu, smA, o);
            smB += __shfl_xor_sync(0xFFFFFFFFu, smB, o);
        }
        const float invA = 1.0f / smA;
        const float invB = 1.0f / smB;

        float oacc[4][4];
        #pragma unroll
        for (int nt = 0; nt < 4; nt++)
            oacc[nt][0] = oacc[nt][1] = oacc[nt][2] = oacc[nt][3] = 0.0f;

        #pragma unroll
        for (int ch = 0; ch < 2; ch++) {
            #pragma unroll
            for (int j9 = 0; j9 < 9; j9++) {
                const int nt = ch * 9 + j9;
                const int cc = j9 * 8 + tg * 2;
                *reinterpret_cast<float2*>(&wscr[g * SCR_S + cc]) =
                    make_float2(f2tf32f(sacc[nt][0]), f2tf32f(sacc[nt][1]));
                *reinterpret_cast<float2*>(&wscr[(g + 8) * SCR_S + cc]) =
                    make_float2(f2tf32f(sacc[nt][2]), f2tf32f(sacc[nt][3]));
            }
            __syncwarp();
            #pragma unroll
            for (int kk = 0; kk < 9; kk++) {
                const int kc = kk * 8;
                const int kglob = ch * 72 + kc;
                unsigned ap[4];
                ap[0] = __float_as_uint(wscr[g * SCR_S + kc + tg]);
                ap[1] = __float_as_uint(wscr[(g + 8) * SCR_S + kc + tg]);
                ap[2] = __float_as_uint(wscr[g * SCR_S + kc + tg + 4]);
                ap[3] = __float_as_uint(wscr[(g + 8) * SCR_S + kc + tg + 4]);
                #pragma unroll
                for (int nt = 0; nt < 4; nt++) {
                    unsigned bf[2];
                    bf[0] = __float_as_uint(vs[(kglob + tg)     * VS_S + nt * 8 + g]);
                    bf[1] = __float_as_uint(vs[(kglob + tg + 4) * VS_S + nt * 8 + g]);
                    mma_tf32(oacc[nt], ap, bf);
                }
            }
            __syncwarp();
        }

        #pragma unroll
        for (int nt = 0; nt < 4; nt++) {
            const int c = nt * 8 + tg * 2;
            float* opA = g_ao + ((size_t)win * NTOK + rb + g) * CDIM + head * HD + c;
            float* opB = g_ao + ((size_t)win * NTOK + rb + 8 + g) * CDIM + head * HD + c;
            *reinterpret_cast<float2*>(opA) =
                make_float2(f2tf32f(oacc[nt][0] * invA), f2tf32f(oacc[nt][1] * invA));
            *reinterpret_cast<float2*>(opB) =
                make_float2(f2tf32f(oacc[nt][2] * invB), f2tf32f(oacc[nt][3] * invB));
        }
    }
}

// ---------------------------------------------------------------------------
// LayerNorm + residual: xout[p] = xin[p] + LN(y[r])*g + b.
// mode 0: p=r; 1: un-window; 2: un-window + un-roll.  One warp per row.
// ---------------------------------------------------------------------------
__global__ void ln_add_kernel(const float* __restrict__ y,
                              const float* __restrict__ g,
                              const float* __restrict__ b,
                              const float* __restrict__ xin,
                              float* __restrict__ xout,
                              int mode) {
    int w = (blockIdx.x * blockDim.x + threadIdx.x) >> 5;
    int lane = threadIdx.x & 31;
    if (w >= MTOK) return;
    size_t p;
    if (mode == 0) {
        p = (size_t)w;
    } else {
        int n = w % NTOK, win = w / NTOK;
        int l = win % NWW, t = win / NWW;
        int tz = t / 8, th = t % 8;
        int z1 = n / 72, h1 = (n % 72) / 12, w1 = n % 12;
        int zr = tz * 2 + z1, hr = th * 6 + h1, wr = l * 12 + w1;
        int z, hh, ww;
        if (mode == 2) { z = (zr + 7) & 7; hh = (hr + 45) % 48; ww = (wr + 186) % 192; }
        else           { z = zr; hh = hr; ww = wr; }
        p = ((size_t)z * 48 + hh) * 192 + ww;
    }
    const float* yr = y + (size_t)w * CDIM;
    float v[6];
    float sum = 0.0f;
    #pragma unroll
    for (int i = 0; i < 6; i++) { v[i] = yr[lane + 32 * i]; sum += v[i]; }
    #pragma unroll
    for (int o = 16; o; o >>= 1) sum += __shfl_xor_sync(0xFFFFFFFFu, sum, o);
    float mu = sum * (1.0f / 192.0f);
    float var = 0.0f;
    #pragma unroll
    for (int i = 0; i < 6; i++) { float d = v[i] - mu; var += d * d; }
    #pragma unroll
    for (int o = 16; o; o >>= 1) var += __shfl_xor_sync(0xFFFFFFFFu, var, o);
    var *= (1.0f / 192.0f);
    float rs = rsqrtf(var + 1e-5f);
    const float* xi = xin + p * CDIM;
    float* xo = xout + p * CDIM;
    #pragma unroll
    for (int i = 0; i < 6; i++) {
        int c = lane + 32 * i;
        xo[c] = xi[c] + (v[i] - mu) * rs * g[c] + b[c];
    }
}

extern "C" void kernel_launch(void* const* d_in, const int* in_sizes, int n_in,
                              void* d_out, int out_size) {
    const float* x_in       = (const float*)d_in[0];
    const float* qkv_w      = (const float*)d_in[1];
    const float* qkv_b      = (const float*)d_in[2];
    const float* proj_w     = (const float*)d_in[3];
    const float* proj_b     = (const float*)d_in[4];
    const float* bias_table = (const float*)d_in[5];
    const float* n1_g       = (const float*)d_in[6];
    const float* n1_b       = (const float*)d_in[7];
    const float* n2_g       = (const float*)d_in[8];
    const float* n2_b       = (const float*)d_in[9];
    const float* w1         = (const float*)d_in[10];
    const float* b1         = (const float*)d_in[11];
    const float* w2         = (const float*)d_in[12];
    const float* b2         = (const float*)d_in[13];
    // d_in[14..16] = Z,H,W scalars (fixed 8,48,192)

    float *gx, *gqkv, *gao, *gtmp, *gh, *gwt;
    cudaGetSymbolAddress((void**)&gx,   g_x);
    cudaGetSymbolAddress((void**)&gqkv, g_qkv);
    cudaGetSymbolAddress((void**)&gao,  g_ao);
    cudaGetSymbolAddress((void**)&gtmp, g_tmp);
    cudaGetSymbolAddress((void**)&gh,   g_h);
    cudaGetSymbolAddress((void**)&gwt,  g_wt);

    round_weights_kernel<<<(221184 + 255) / 256, 256>>>(qkv_w,  gwt + WQ_OFF, 221184);
    round_weights_kernel<<<( 73728 + 255) / 256, 256>>>(proj_w, gwt + WP_OFF,  73728);
    round_weights_kernel<<<(294912 + 255) / 256, 256>>>(w1,     gwt + W1_OFF, 294912);
    round_weights_kernel<<<(294912 + 255) / 256, 256>>>(w2,     gwt + W2_OFF, 294912);

    {
        size_t total = (size_t)2 * TWIN * NHEAD * NTOK * NTOK;
        biasmask_kernel<<<(unsigned)((total + 255) / 256), 256>>>(bias_table);
    }

    cudaFuncSetAttribute(mma_gemm_kernel<0,1,1,1>, cudaFuncAttributeMaxDynamicSharedMemorySize, GEMM_SMEM);
    cudaFuncSetAttribute(mma_gemm_kernel<0,0,0,0>, cudaFuncAttributeMaxDynamicSharedMemorySize, GEMM_SMEM);
    cudaFuncSetAttribute(mma_gemm_kernel<1,0,1,1>, cudaFuncAttributeMaxDynamicSharedMemorySize, GEMM_SMEM);
    cudaFuncSetAttribute(attn_mma_kernel, cudaFuncAttributeMaxDynamicSharedMemorySize, ATTN_SMEM);

    for (int L = 0; L < 2; L++) {
        const float* xsrc = (L == 0) ? x_in : gx;

        // QKV (fused window gather, A cvt, outputs rounded for attn)
        mma_gemm_kernel<0,1,1,1><<<dim3(QKVN / 64, MTOK / 128), 128, GEMM_SMEM>>>(
            xsrc, gwt + WQ_OFF + (size_t)L * CDIM * QKVN, qkv_b + (size_t)L * QKVN,
            gqkv, CDIM, QKVN, L);

        attn_mma_kernel<<<dim3(NWIN, NHEAD), 128, ATTN_SMEM>>>(L);

        // proj (A pre-rounded by attn -> no cvt)
        mma_gemm_kernel<0,0,0,0><<<dim3(CDIM / 64, MTOK / 128), 128, GEMM_SMEM>>>(
            gao, gwt + WP_OFF + (size_t)L * CDIM * CDIM, proj_b + (size_t)L * CDIM,
            gtmp, CDIM, CDIM, 0);

        ln_add_kernel<<<(MTOK * 32 + 255) / 256, 256>>>(
            gtmp, n1_g + (size_t)L * CDIM, n1_b + (size_t)L * CDIM,
            xsrc, gx, L ? 2 : 1);

        // MLP up (A = residual fp32 -> cvt; gelu; outputs rounded for down-proj)
        mma_gemm_kernel<1,0,1,1><<<dim3(FFN / 64, MTOK / 128), 128, GEMM_SMEM>>>(
            gx, gwt + W1_OFF + (size_t)L * CDIM * FFN, b1 + (size_t)L * FFN,
            gh, CDIM, FFN, 0);

        // MLP down (A pre-rounded -> no cvt)
        mma_gemm_kernel<0,0,0,0><<<dim3(CDIM / 64, MTOK / 128), 128, GEMM_SMEM>>>(
            gh, gwt + W2_OFF + (size_t)L * FFN * CDIM, b2 + (size_t)L * CDIM,
            gtmp, FFN, CDIM, 0);

        float* xo = (L == 1) ? (float*)d_out : gx;
        ln_add_kernel<<<(MTOK * 32 + 255) / 256, 256>>>(
            gtmp, n2_g + (size_t)L * CDIM, n2_b + (size_t)L * CDIM,
            gx, xo, 0);
    }
}

// round 7
// speedup vs baseline: 1.3072x; 1.3072x over previous
#include <cuda_runtime.h>
#include <cuda_bf16.h>
#include <math.h>

#define MTOK   73728
#define CDIM   192
#define NHEAD  6
#define HD     32
#define NTOK   144
#define NWIN   512
#define TWIN   32
#define NWW    16
#define NB     3312
#define QKVN   576
#define FFN    768

__device__ float g_x  [(size_t)MTOK * CDIM];
__device__ float g_qkv[(size_t)MTOK * QKVN];
__device__ float g_ao [(size_t)MTOK * CDIM];
__device__ float g_tmp[(size_t)MTOK * CDIM];
__device__ float g_h  [(size_t)MTOK * FFN];
__device__ float g_bm [(size_t)2 * TWIN * NHEAD * NTOK * NTOK];
// tf32-pre-rounded weights: qkv | proj | w1 | w2  (both layers)
#define WQ_OFF 0
#define WP_OFF 221184
#define W1_OFF 294912
#define W2_OFF 589824
__device__ float g_wt [884736];

// ---------------------------------------------------------------------------
// helpers
// ---------------------------------------------------------------------------
__device__ __forceinline__ unsigned f2tf32(float x) {
    unsigned r;
    asm("cvt.rna.tf32.f32 %0, %1;" : "=r"(r) : "f"(x));
    return r;
}
__device__ __forceinline__ float f2tf32f(float x) { return __uint_as_float(f2tf32(x)); }

__device__ __forceinline__ void mma_tf32(float* d, const unsigned* a, const unsigned* b) {
    asm volatile(
        "mma.sync.aligned.m16n8k8.row.col.f32.tf32.tf32.f32 "
        "{%0,%1,%2,%3}, {%4,%5,%6,%7}, {%8,%9}, {%0,%1,%2,%3};\n"
        : "+f"(d[0]), "+f"(d[1]), "+f"(d[2]), "+f"(d[3])
        : "r"(a[0]), "r"(a[1]), "r"(a[2]), "r"(a[3]),
          "r"(b[0]), "r"(b[1]));
}

__device__ __forceinline__ unsigned smaddr(const void* p) {
    return (unsigned)__cvta_generic_to_shared(p);
}
#define CPA16(dst, src) asm volatile("cp.async.cg.shared.global [%0], [%1], 16;" :: "r"(dst), "l"(src))
#define CPCOMMIT()      asm volatile("cp.async.commit_group;")
#define CPWAIT1()       asm volatile("cp.async.wait_group 1;")

__device__ __forceinline__ float gelu_exact(float v) {
    return 0.5f * v * (1.0f + erff(v * 0.70710678118654752f));
}

__global__ void round_weights_kernel(const float* __restrict__ src,
                                     float* __restrict__ dst, int n) {
    int i = blockIdx.x * blockDim.x + threadIdx.x;
    if (i < n) dst[i] = f2tf32f(src[i]);
}

// ---------------------------------------------------------------------------
// Dense (relative-position bias + shift mask)
// ---------------------------------------------------------------------------
__global__ void biasmask_kernel(const float* __restrict__ table) {
    size_t idx = (size_t)blockIdx.x * blockDim.x + threadIdx.x;
    size_t total = (size_t)2 * TWIN * NHEAD * NTOK * NTOK;
    if (idx >= total) return;
    int m = idx % NTOK; size_t r = idx / NTOK;
    int n = r % NTOK;   r /= NTOK;
    int head = r % NHEAD; r /= NHEAD;
    int t = r % TWIN;   int L = (int)(r / TWIN);
    int z1 = n / 72, h1 = (n % 72) / 12, w1 = n % 12;
    int z2 = m / 72, h2 = (m % 72) / 12, w2 = m % 12;
    int pos = 828 * (z1 + 2 * z2) + 23 * (h1 + 6 * h2) + (w1 - w2 + 11);
    float v = table[(((size_t)L * NB + pos) * TWIN + t) * NHEAD + head];
    if (L == 1) {
        int tz = t / 8, th = t % 8;
        int idn = (((tz * 2 + z1) >= 1) ? 2 : 0) + (((th * 6 + h1) >= 3) ? 1 : 0);
        int idm = (((tz * 2 + z2) >= 1) ? 2 : 0) + (((th * 6 + h2) >= 3) ? 1 : 0);
        if (idn != idm) v += -10000.0f;
    }
    g_bm[idx] = v;
}

// ---------------------------------------------------------------------------
// tf32 GEMM (R5 tiling, proven): BM=128, BN=64, BK=32, 256 thr / 8 warps
// (4m x 2n), warp tile 32x32, acc[2][4][4]=32 regs. 2-stage cp.async.
// B pre-rounded tf32 (raw bits). ACVT: cvt A fragments (fp32 A).
// ROUND: round outputs to tf32 for the next consumer.
// GATHER: A rows window-remapped; `rolled` selects shifted mapping.
// ---------------------------------------------------------------------------
#define ASTG (128 * 36)
#define BSTG (32 * 72)
#define GEMM_SMEM ((2 * ASTG + 2 * BSTG) * 4)   // 55296 B

template <int EPI, int GATHER, int ACVT, int ROUND>
__global__ void __launch_bounds__(256, 3)
mma_gemm_kernel(const float* __restrict__ A,
                const float* __restrict__ B,
                const float* __restrict__ bias,
                float* __restrict__ Cm,
                int K, int Nn, int rolled) {
    extern __shared__ float dsm[];
    float* As = dsm;
    float* Bs = dsm + 2 * ASTG;

    const int tid  = threadIdx.x;
    const int lane = tid & 31;
    const int wid  = tid >> 5;
    const int wm   = wid >> 1;          // 0..3
    const int wn   = wid & 1;           // 0..1
    const int g    = lane >> 2;
    const int tg   = lane & 3;
    const int m0   = blockIdx.y * 128;
    const int n0   = blockIdx.x * 64;

    const int arow0 = tid >> 3;        // + 32*i, i<4
    const int akc4  = tid & 7;
    const int brow0 = tid >> 4;        // + 16*i, i<2
    const int bc4   = tid & 15;

    const float* aSrc[4];
    #pragma unroll
    for (int i = 0; i < 4; i++) {
        int r = m0 + arow0 + 32 * i;
        size_t p;
        if (GATHER) {
            int n = r % NTOK, win = r / NTOK;
            int l = win % NWW, t = win / NWW;
            int tz = t / 8, th = t % 8;
            int z1 = n / 72, h1 = (n % 72) / 12, w1 = n % 12;
            int zr = tz * 2 + z1, hr = th * 6 + h1, wr = l * 12 + w1;
            int z, hh, ww;
            if (rolled) { z = (zr + 7) & 7; hh = (hr + 45) % 48; ww = (wr + 186) % 192; }
            else        { z = zr; hh = hr; ww = wr; }
            p = ((size_t)z * 48 + hh) * 192 + ww;
        } else {
            p = (size_t)r;
        }
        aSrc[i] = A + p * K + akc4 * 4;
    }
    const float* bSrc = B + (size_t)brow0 * Nn + n0 + bc4 * 4;

    float acc[2][4][4];
    #pragma unroll
    for (int mt = 0; mt < 2; mt++)
        #pragma unroll
        for (int nt = 0; nt < 4; nt++)
            #pragma unroll
            for (int i = 0; i < 4; i++) acc[mt][nt][i] = 0.0f;

    // prologue: stages 0,1
    #pragma unroll
    for (int s = 0; s < 2; s++) {
        float* as = As + s * ASTG;
        float* bs = Bs + s * BSTG;
        const int k0 = s * 32;
        #pragma unroll
        for (int i = 0; i < 4; i++)
            CPA16(smaddr(as + (arow0 + 32 * i) * 36 + akc4 * 4), aSrc[i] + k0);
        #pragma unroll
        for (int i = 0; i < 2; i++)
            CPA16(smaddr(bs + (brow0 + 16 * i) * 72 + bc4 * 4),
                  bSrc + (size_t)(k0 + 16 * i) * Nn);
        CPCOMMIT();
    }

    const int iters = K >> 5;
    for (int it = 0; it < iters; it++) {
        const int cur = it & 1;
        CPWAIT1();
        __syncthreads();

        const float* as = As + cur * ASTG;
        const float* bs = Bs + cur * BSTG;
        #pragma unroll
        for (int ks = 0; ks < 4; ks++) {
            const int kk = ks * 8;
            unsigned af[2][4], bf[4][2];
            #pragma unroll
            for (int mt = 0; mt < 2; mt++) {
                int rbse = wm * 32 + mt * 16;
                if (ACVT) {
                    af[mt][0] = f2tf32(as[(rbse + g)     * 36 + kk + tg]);
                    af[mt][1] = f2tf32(as[(rbse + 8 + g) * 36 + kk + tg]);
                    af[mt][2] = f2tf32(as[(rbse + g)     * 36 + kk + tg + 4]);
                    af[mt][3] = f2tf32(as[(rbse + 8 + g) * 36 + kk + tg + 4]);
                } else {
                    af[mt][0] = __float_as_uint(as[(rbse + g)     * 36 + kk + tg]);
                    af[mt][1] = __float_as_uint(as[(rbse + 8 + g) * 36 + kk + tg]);
                    af[mt][2] = __float_as_uint(as[(rbse + g)     * 36 + kk + tg + 4]);
                    af[mt][3] = __float_as_uint(as[(rbse + 8 + g) * 36 + kk + tg + 4]);
                }
            }
            #pragma unroll
            for (int nt = 0; nt < 4; nt++) {
                int cb = wn * 32 + nt * 8;
                bf[nt][0] = __float_as_uint(bs[(kk + tg)     * 72 + cb + g]);
                bf[nt][1] = __float_as_uint(bs[(kk + 4 + tg) * 72 + cb + g]);
            }
            #pragma unroll
            for (int mt = 0; mt < 2; mt++)
                #pragma unroll
                for (int nt = 0; nt < 4; nt++)
                    mma_tf32(acc[mt][nt], af[mt], bf[nt]);
        }
        __syncthreads();

        const int k0n = (it + 2) << 5;
        if (k0n < K) {
            float* asw = As + cur * ASTG;
            float* bsw = Bs + cur * BSTG;
            #pragma unroll
            for (int i = 0; i < 4; i++)
                CPA16(smaddr(asw + (arow0 + 32 * i) * 36 + akc4 * 4), aSrc[i] + k0n);
            #pragma unroll
            for (int i = 0; i < 2; i++)
                CPA16(smaddr(bsw + (brow0 + 16 * i) * 72 + bc4 * 4),
                      bSrc + (size_t)(k0n + 16 * i) * Nn);
        }
        CPCOMMIT();
    }

    #pragma unroll
    for (int mt = 0; mt < 2; mt++) {
        int r0 = m0 + wm * 32 + mt * 16 + g;
        #pragma unroll
        for (int nt = 0; nt < 4; nt++) {
            int c = n0 + wn * 32 + nt * 8 + tg * 2;
            float b0 = bias[c], b1 = bias[c + 1];
            float v0 = acc[mt][nt][0] + b0;
            float v1 = acc[mt][nt][1] + b1;
            float v2 = acc[mt][nt][2] + b0;
            float v3 = acc[mt][nt][3] + b1;
            if (EPI == 1) {
                v0 = gelu_exact(v0); v1 = gelu_exact(v1);
                v2 = gelu_exact(v2); v3 = gelu_exact(v3);
            }
            if (ROUND) {
                v0 = f2tf32f(v0); v1 = f2tf32f(v1);
                v2 = f2tf32f(v2); v3 = f2tf32f(v3);
            }
            *reinterpret_cast<float2*>(Cm + (size_t)r0 * Nn + c)       = make_float2(v0, v1);
            *reinterpret_cast<float2*>(Cm + (size_t)(r0 + 8) * Nn + c) = make_float2(v2, v3);
        }
    }
}

// ---------------------------------------------------------------------------
// Tensor-core window attention. qkv arrives pre-rounded to tf32 -> zero cvts
// on q/k/v. 1/sqrt(32) scale folded into the bias fmaf after the S-mma.
// Output rounded to tf32 (proj GEMM consumes raw bits).
// ---------------------------------------------------------------------------
#define KS_S  36
#define VS_S  40
#define SCR_S 76
#define ATTN_SMEM ((NTOK * KS_S + NTOK * VS_S + 4 * 16 * SCR_S) * 4)

__global__ void __launch_bounds__(128, 3) attn_mma_kernel(int L) {
    const int win  = blockIdx.x;
    const int head = blockIdx.y;
    const int t    = win >> 4;
    extern __shared__ float sm[];
    float* ks  = sm;                        // [144][36]
    float* vs  = ks + NTOK * KS_S;          // [144][40]
    float* scr = vs + NTOK * VS_S;          // 4 x [16][76]

    const int tid  = threadIdx.x;
    const int lane = tid & 31;
    const int wid  = tid >> 5;
    const int g    = lane >> 2;
    const int tg   = lane & 3;

    const float* base = g_qkv + (size_t)win * NTOK * QKVN;
    const int hc4 = head * 8;
    for (int idx = tid; idx < NTOK * 8; idx += 128) {
        int row = idx >> 3, j = idx & 7;
        const float4* rp = reinterpret_cast<const float4*>(base + (size_t)row * QKVN);
        *reinterpret_cast<float4*>(&ks[row * KS_S + j * 4]) = rp[48 + hc4 + j];
        *reinterpret_cast<float4*>(&vs[row * VS_S + j * 4]) = rp[96 + hc4 + j];
    }
    __syncthreads();

    const float* bmb = g_bm + (((size_t)L * TWIN + t) * NHEAD + head) * NTOK * NTOK;
    float* wscr = scr + wid * 16 * SCR_S;
    const float sc = 0.17677669529663687f;   // 1/sqrt(32)

    for (int mt = wid; mt < 9; mt += 4) {
        const int rb = mt * 16;

        const float* qA = g_qkv + (size_t)(win * NTOK + rb + g) * QKVN + head * HD;
        const float* qB = g_qkv + (size_t)(win * NTOK + rb + 8 + g) * QKVN + head * HD;
        unsigned aq[4][4];
        #pragma unroll
        for (int kk4 = 0; kk4 < 4; kk4++) {
            const int kc = kk4 * 8;
            aq[kk4][0] = __float_as_uint(qA[kc + tg]);
            aq[kk4][1] = __float_as_uint(qB[kc + tg]);
            aq[kk4][2] = __float_as_uint(qA[kc + tg + 4]);
            aq[kk4][3] = __float_as_uint(qB[kc + tg + 4]);
        }

        float sacc[18][4];
        #pragma unroll
        for (int nt = 0; nt < 18; nt++) {
            sacc[nt][0] = sacc[nt][1] = sacc[nt][2] = sacc[nt][3] = 0.0f;
            const int cb = nt * 8;
            #pragma unroll
            for (int kk4 = 0; kk4 < 4; kk4++) {
                const int kc = kk4 * 8;
                unsigned bf[2];
                bf[0] = __float_as_uint(ks[(cb + g) * KS_S + kc + tg]);
                bf[1] = __float_as_uint(ks[(cb + g) * KS_S + kc + tg + 4]);
                mma_tf32(sacc[nt], aq[kk4], bf);
            }
            const float2 bA = *reinterpret_cast<const float2*>(
                bmb + (size_t)(rb + g) * NTOK + cb + tg * 2);
            const float2 bB = *reinterpret_cast<const float2*>(
                bmb + (size_t)(rb + 8 + g) * NTOK + cb + tg * 2);
            sacc[nt][0] = fmaf(sacc[nt][0], sc, bA.x);
            sacc[nt][1] = fmaf(sacc[nt][1], sc, bA.y);
            sacc[nt][2] = fmaf(sacc[nt][2], sc, bB.x);
            sacc[nt][3] = fmaf(sacc[nt][3], sc, bB.y);
        }

        float mxA = -1e30f, mxB = -1e30f;
        #pragma unroll
        for (int nt = 0; nt < 18; nt++) {
            mxA = fmaxf(mxA, fmaxf(sacc[nt][0], sacc[nt][1]));
            mxB = fmaxf(mxB, fmaxf(sacc[nt][2], sacc[nt][3]));
        }
        #pragma unroll
        for (int o = 1; o <= 2; o <<= 1) {
            mxA = fmaxf(mxA, __shfl_xor_sync(0xFFFFFFFFu, mxA, o));
            mxB = fmaxf(mxB, __shfl_xor_sync(0xFFFFFFFFu, mxB, o));
        }
        float smA = 0.0f, smB = 0.0f;
        #pragma unroll
        for (int nt = 0; nt < 18; nt++) {
            sacc[nt][0] = __expf(sacc[nt][0] - mxA);
            sacc[nt][1] = __expf(sacc[nt][1] - mxA);
            sacc[nt][2] = __expf(sacc[nt][2] - mxB);
            sacc[nt][3] = __expf(sacc[nt][3] - mxB);
            smA += sacc[nt][0] + sacc[nt][1];
            smB += sacc[nt][2] + sacc[nt][3];
        }
        #pragma unroll
        for (int o = 1; o <= 2; o <<= 1) {
            smA += __shfl_xor_sync(0xFFFFFFFFu, smA, o);
            smB += __shfl_xor_sync(0xFFFFFFFFu, smB, o);
        }
        const float invA = 1.0f / smA;
        const float invB = 1.0f / smB;

        float oacc[4][4];
        #pragma unroll
        for (int nt = 0; nt < 4; nt++)
            oacc[nt][0] = oacc[nt][1] = oacc[nt][2] = oacc[nt][3] = 0.0f;

        #pragma unroll
        for (int ch = 0; ch < 2; ch++) {
            #pragma unroll
            for (int j9 = 0; j9 < 9; j9++) {
                const int nt = ch * 9 + j9;
                const int cc = j9 * 8 + tg * 2;
                *reinterpret_cast<float2*>(&wscr[g * SCR_S + cc]) =
                    make_float2(f2tf32f(sacc[nt][0]), f2tf32f(sacc[nt][1]));
                *reinterpret_cast<float2*>(&wscr[(g + 8) * SCR_S + cc]) =
                    make_float2(f2tf32f(sacc[nt][2]), f2tf32f(sacc[nt][3]));
            }
            __syncwarp();
            #pragma unroll
            for (int kk = 0; kk < 9; kk++) {
                const int kc = kk * 8;
                const int kglob = ch * 72 + kc;
                unsigned ap[4];
                ap[0] = __float_as_uint(wscr[g * SCR_S + kc + tg]);
                ap[1] = __float_as_uint(wscr[(g + 8) * SCR_S + kc + tg]);
                ap[2] = __float_as_uint(wscr[g * SCR_S + kc + tg + 4]);
                ap[3] = __float_as_uint(wscr[(g + 8) * SCR_S + kc + tg + 4]);
                #pragma unroll
                for (int nt = 0; nt < 4; nt++) {
                    unsigned bf[2];
                    bf[0] = __float_as_uint(vs[(kglob + tg)     * VS_S + nt * 8 + g]);
                    bf[1] = __float_as_uint(vs[(kglob + tg + 4) * VS_S + nt * 8 + g]);
                    mma_tf32(oacc[nt], ap, bf);
                }
            }
            __syncwarp();
        }

        #pragma unroll
        for (int nt = 0; nt < 4; nt++) {
            const int c = nt * 8 + tg * 2;
            float* opA = g_ao + ((size_t)win * NTOK + rb + g) * CDIM + head * HD + c;
            float* opB = g_ao + ((size_t)win * NTOK + rb + 8 + g) * CDIM + head * HD + c;
            *reinterpret_cast<float2*>(opA) =
                make_float2(f2tf32f(oacc[nt][0] * invA), f2tf32f(oacc[nt][1] * invA));
            *reinterpret_cast<float2*>(opB) =
                make_float2(f2tf32f(oacc[nt][2] * invB), f2tf32f(oacc[nt][3] * invB));
        }
    }
}

// ---------------------------------------------------------------------------
// LayerNorm + residual: xout[p] = xin[p] + LN(y[r])*g + b.
// mode 0: p=r; 1: un-window; 2: un-window + un-roll.  One warp per row.
// ---------------------------------------------------------------------------
__global__ void ln_add_kernel(const float* __restrict__ y,
                              const float* __restrict__ g,
                              const float* __restrict__ b,
                              const float* __restrict__ xin,
                              float* __restrict__ xout,
                              int mode) {
    int w = (blockIdx.x * blockDim.x + threadIdx.x) >> 5;
    int lane = threadIdx.x & 31;
    if (w >= MTOK) return;
    size_t p;
    if (mode == 0) {
        p = (size_t)w;
    } else {
        int n = w % NTOK, win = w / NTOK;
        int l = win % NWW, t = win / NWW;
        int tz = t / 8, th = t % 8;
        int z1 = n / 72, h1 = (n % 72) / 12, w1 = n % 12;
        int zr = tz * 2 + z1, hr = th * 6 + h1, wr = l * 12 + w1;
        int z, hh, ww;
        if (mode == 2) { z = (zr + 7) & 7; hh = (hr + 45) % 48; ww = (wr + 186) % 192; }
        else           { z = zr; hh = hr; ww = wr; }
        p = ((size_t)z * 48 + hh) * 192 + ww;
    }
    const float* yr = y + (size_t)w * CDIM;
    float v[6];
    float sum = 0.0f;
    #pragma unroll
    for (int i = 0; i < 6; i++) { v[i] = yr[lane + 32 * i]; sum += v[i]; }
    #pragma unroll
    for (int o = 16; o; o >>= 1) sum += __shfl_xor_sync(0xFFFFFFFFu, sum, o);
    float mu = sum * (1.0f / 192.0f);
    float var = 0.0f;
    #pragma unroll
    for (int i = 0; i < 6; i++) { float d = v[i] - mu; var += d * d; }
    #pragma unroll
    for (int o = 16; o; o >>= 1) var += __shfl_xor_sync(0xFFFFFFFFu, var, o);
    var *= (1.0f / 192.0f);
    float rs = rsqrtf(var + 1e-5f);
    const float* xi = xin + p * CDIM;
    float* xo = xout + p * CDIM;
    #pragma unroll
    for (int i = 0; i < 6; i++) {
        int c = lane + 32 * i;
        xo[c] = xi[c] + (v[i] - mu) * rs * g[c] + b[c];
    }
}

extern "C" void kernel_launch(void* const* d_in, const int* in_sizes, int n_in,
                              void* d_out, int out_size) {
    const float* x_in       = (const float*)d_in[0];
    const float* qkv_w      = (const float*)d_in[1];
    const float* qkv_b      = (const float*)d_in[2];
    const float* proj_w     = (const float*)d_in[3];
    const float* proj_b     = (const float*)d_in[4];
    const float* bias_table = (const float*)d_in[5];
    const float* n1_g       = (const float*)d_in[6];
    const float* n1_b       = (const float*)d_in[7];
    const float* n2_g       = (const float*)d_in[8];
    const float* n2_b       = (const float*)d_in[9];
    const float* w1         = (const float*)d_in[10];
    const float* b1         = (const float*)d_in[11];
    const float* w2         = (const float*)d_in[12];
    const float* b2         = (const float*)d_in[13];
    // d_in[14..16] = Z,H,W scalars (fixed 8,48,192)

    float *gx, *gqkv, *gao, *gtmp, *gh, *gwt;
    cudaGetSymbolAddress((void**)&gx,   g_x);
    cudaGetSymbolAddress((void**)&gqkv, g_qkv);
    cudaGetSymbolAddress((void**)&gao,  g_ao);
    cudaGetSymbolAddress((void**)&gtmp, g_tmp);
    cudaGetSymbolAddress((void**)&gh,   g_h);
    cudaGetSymbolAddress((void**)&gwt,  g_wt);

    round_weights_kernel<<<(221184 + 255) / 256, 256>>>(qkv_w,  gwt + WQ_OFF, 221184);
    round_weights_kernel<<<( 73728 + 255) / 256, 256>>>(proj_w, gwt + WP_OFF,  73728);
    round_weights_kernel<<<(294912 + 255) / 256, 256>>>(w1,     gwt + W1_OFF, 294912);
    round_weights_kernel<<<(294912 + 255) / 256, 256>>>(w2,     gwt + W2_OFF, 294912);

    {
        size_t total = (size_t)2 * TWIN * NHEAD * NTOK * NTOK;
        biasmask_kernel<<<(unsigned)((total + 255) / 256), 256>>>(bias_table);
    }

    cudaFuncSetAttribute(mma_gemm_kernel<0,1,1,1>, cudaFuncAttributeMaxDynamicSharedMemorySize, GEMM_SMEM);
    cudaFuncSetAttribute(mma_gemm_kernel<0,0,0,0>, cudaFuncAttributeMaxDynamicSharedMemorySize, GEMM_SMEM);
    cudaFuncSetAttribute(mma_gemm_kernel<1,0,1,1>, cudaFuncAttributeMaxDynamicSharedMemorySize, GEMM_SMEM);
    cudaFuncSetAttribute(attn_mma_kernel, cudaFuncAttributeMaxDynamicSharedMemorySize, ATTN_SMEM);

    for (int L = 0; L < 2; L++) {
        const float* xsrc = (L == 0) ? x_in : gx;

        // QKV (fused window gather, A cvt, outputs rounded for attn)
        mma_gemm_kernel<0,1,1,1><<<dim3(QKVN / 64, MTOK / 128), 256, GEMM_SMEM>>>(
            xsrc, gwt + WQ_OFF + (size_t)L * CDIM * QKVN, qkv_b + (size_t)L * QKVN,
            gqkv, CDIM, QKVN, L);

        attn_mma_kernel<<<dim3(NWIN, NHEAD), 128, ATTN_SMEM>>>(L);

        // proj (A pre-rounded by attn -> no cvt)
        mma_gemm_kernel<0,0,0,0><<<dim3(CDIM / 64, MTOK / 128), 256, GEMM_SMEM>>>(
            gao, gwt + WP_OFF + (size_t)L * CDIM * CDIM, proj_b + (size_t)L * CDIM,
            gtmp, CDIM, CDIM, 0);

        ln_add_kernel<<<(MTOK * 32 + 255) / 256, 256>>>(
            gtmp, n1_g + (size_t)L * CDIM, n1_b + (size_t)L * CDIM,
            xsrc, gx, L ? 2 : 1);

        // MLP up (A = residual fp32 -> cvt; gelu; outputs rounded)
        mma_gemm_kernel<1,0,1,1><<<dim3(FFN / 64, MTOK / 128), 256, GEMM_SMEM>>>(
            gx, gwt + W1_OFF + (size_t)L * CDIM * FFN, b1 + (size_t)L * FFN,
            gh, CDIM, FFN, 0);

        // MLP down (A pre-rounded -> no cvt)
        mma_gemm_kernel<0,0,0,0><<<dim3(CDIM / 64, MTOK / 128), 256, GEMM_SMEM>>>(
            gh, gwt + W2_OFF + (size_t)L * FFN * CDIM, b2 + (size_t)L * CDIM,
            gtmp, FFN, CDIM, 0);

        float* xo = (L == 1) ? (float*)d_out : gx;
        ln_add_kernel<<<(MTOK * 32 + 255) / 256, 256>>>(
            gtmp, n2_g + (size_t)L * CDIM, n2_b + (size_t)L * CDIM,
            gx, xo, 0);
    }
}

// round 9
// speedup vs baseline: 1.7024x; 1.3023x over previous
#include <cuda_runtime.h>
#include <cuda_fp16.h>
#include <math.h>

#define MTOK   73728
#define CDIM   192
#define NHEAD  6
#define HD     32
#define NTOK   144
#define NWIN   512
#define TWIN   32
#define NWW    16
#define NB     3312
#define QKVN   576
#define FFN    768

// fp32 buffers (residual stream, LN temp, bias table)
__device__ float  g_x   [(size_t)MTOK * CDIM];
__device__ float  g_tmp [(size_t)MTOK * CDIM];
__device__ float  g_bm  [(size_t)2 * TWIN * NHEAD * NTOK * NTOK];
// f16 activation buffers
__device__ __half g_xh16 [(size_t)MTOK * CDIM];
__device__ __half g_qkv16[(size_t)MTOK * QKVN];
__device__ __half g_ao16 [(size_t)MTOK * CDIM];
__device__ __half g_h16  [(size_t)MTOK * FFN];
// f16 transposed weights [N][K]: qkv | proj | w1 | w2 (both layers)
#define WQ_OFF 0
#define WP_OFF 221184
#define W1_OFF 294912
#define W2_OFF 589824
__device__ __half g_wt16[884736];

// ---------------------------------------------------------------------------
// helpers
// ---------------------------------------------------------------------------
__device__ __forceinline__ void mma_f16(float* d, const unsigned* a, const unsigned* b) {
    asm volatile(
        "mma.sync.aligned.m16n8k16.row.col.f32.f16.f16.f32 "
        "{%0,%1,%2,%3}, {%4,%5,%6,%7}, {%8,%9}, {%0,%1,%2,%3};\n"
        : "+f"(d[0]), "+f"(d[1]), "+f"(d[2]), "+f"(d[3])
        : "r"(a[0]), "r"(a[1]), "r"(a[2]), "r"(a[3]),
          "r"(b[0]), "r"(b[1]));
}

__device__ __forceinline__ unsigned ldh2u(const __half* p) {
    return *reinterpret_cast<const unsigned*>(p);
}

__device__ __forceinline__ unsigned smaddr(const void* p) {
    return (unsigned)__cvta_generic_to_shared(p);
}
#define CPA16(dst, src) asm volatile("cp.async.cg.shared.global [%0], [%1], 16;" :: "r"(dst), "l"(src))
#define CPCOMMIT()      asm volatile("cp.async.commit_group;")
#define CPWAIT1()       asm volatile("cp.async.wait_group 1;")

__device__ __forceinline__ float gelu_exact(float v) {
    return 0.5f * v * (1.0f + erff(v * 0.70710678118654752f));
}

// ---------------------------------------------------------------------------
// Prep: tiled transpose + cvt fp32 [K][N] -> f16 [N][K]
// ---------------------------------------------------------------------------
__global__ void transpose_cvt_kernel(const float* __restrict__ src,
                                     __half* __restrict__ dst, int K, int N) {
    __shared__ float t[32][33];
    const int n0 = blockIdx.x * 32, k0 = blockIdx.y * 32;
    const int tx = threadIdx.x, ty = threadIdx.y;   // 32 x 8
    #pragma unroll
    for (int i = 0; i < 32; i += 8)
        t[ty + i][tx] = src[(size_t)(k0 + ty + i) * N + n0 + tx];
    __syncthreads();
    #pragma unroll
    for (int i = 0; i < 32; i += 8)
        dst[(size_t)(n0 + ty + i) * K + k0 + tx] = __float2half_rn(t[tx][ty + i]);
}

__global__ void cvt_f16_kernel(const float* __restrict__ src,
                               __half* __restrict__ dst, int n) {
    int i = blockIdx.x * blockDim.x + threadIdx.x;
    if (i < n) dst[i] = __float2half_rn(src[i]);
}

// ---------------------------------------------------------------------------
// Dense (relative-position bias + shift mask)
// ---------------------------------------------------------------------------
__global__ void biasmask_kernel(const float* __restrict__ table) {
    size_t idx = (size_t)blockIdx.x * blockDim.x + threadIdx.x;
    size_t total = (size_t)2 * TWIN * NHEAD * NTOK * NTOK;
    if (idx >= total) return;
    int m = idx % NTOK; size_t r = idx / NTOK;
    int n = r % NTOK;   r /= NTOK;
    int head = r % NHEAD; r /= NHEAD;
    int t = r % TWIN;   int L = (int)(r / TWIN);
    int z1 = n / 72, h1 = (n % 72) / 12, w1 = n % 12;
    int z2 = m / 72, h2 = (m % 72) / 12, w2 = m % 12;
    int pos = 828 * (z1 + 2 * z2) + 23 * (h1 + 6 * h2) + (w1 - w2 + 11);
    float v = table[(((size_t)L * NB + pos) * TWIN + t) * NHEAD + head];
    if (L == 1) {
        int tz = t / 8, th = t % 8;
        int idn = (((tz * 2 + z1) >= 1) ? 2 : 0) + (((th * 6 + h1) >= 3) ? 1 : 0);
        int idm = (((tz * 2 + z2) >= 1) ? 2 : 0) + (((th * 6 + h2) >= 3) ? 1 : 0);
        if (idn != idm) v += -10000.0f;
    }
    g_bm[idx] = v;
}

// ---------------------------------------------------------------------------
// f16 GEMM (m16n8k16, fp32 accum): BM=128, BN=64, BK=32, 256 thr / 8 warps
// (4m x 2n), warp tile 32x32 -> per k16-step: 16 LDS.32 + 8 mma.
// A f16 [M][K]; B f16 [N][K] (pre-transposed weights). 2-stage cp.async.
// OUTH: store outputs as f16 (else fp32). GATHER: window-remap A rows.
// smem stride 40 f16 -> conflict-free fragment loads (bank = g*20+tg).
// ---------------------------------------------------------------------------
#define ASTG16 (128 * 40)
#define BSTG16 (64 * 40)
#define GEMM_SMEM16 ((2 * ASTG16 + 2 * BSTG16) * 2)   // 30720 B

template <int EPI, int GATHER, int OUTH>
__global__ void __launch_bounds__(256, 3)
hgemm_kernel(const __half* __restrict__ A,
             const __half* __restrict__ B,
             const float* __restrict__ bias,
             void* __restrict__ Cout,
             int K, int Nn, int rolled) {
    extern __shared__ __half hsm[];
    __half* As = hsm;
    __half* Bs = hsm + 2 * ASTG16;

    const int tid  = threadIdx.x;
    const int lane = tid & 31;
    const int wid  = tid >> 5;
    const int wm   = wid >> 1;          // 0..3
    const int wn   = wid & 1;           // 0..1
    const int g    = lane >> 2;
    const int tg   = lane & 3;
    const int m0   = blockIdx.y * 128;
    const int n0   = blockIdx.x * 64;

    // copy roles: A row = tid>>1, 2 x 16B chunks; B row = tid>>2, 1 x 16B
    const int arow = tid >> 1;
    const int ac0  = (tid & 1) * 2;
    const int brow = tid >> 2;
    const int bchk = tid & 3;

    size_t arowp;
    {
        int r = m0 + arow;
        if (GATHER) {
            int n = r % NTOK, win = r / NTOK;
            int l = win % NWW, t = win / NWW;
            int tz = t / 8, th = t % 8;
            int z1 = n / 72, h1 = (n % 72) / 12, w1 = n % 12;
            int zr = tz * 2 + z1, hr = th * 6 + h1, wr = l * 12 + w1;
            int z, hh, ww;
            if (rolled) { z = (zr + 7) & 7; hh = (hr + 45) % 48; ww = (wr + 186) % 192; }
            else        { z = zr; hh = hr; ww = wr; }
            arowp = ((size_t)z * 48 + hh) * 192 + ww;
        } else {
            arowp = (size_t)r;
        }
    }
    const __half* aSrc = A + arowp * K;
    const __half* bSrc = B + (size_t)(n0 + brow) * K;

    float acc[2][4][4];
    #pragma unroll
    for (int mt = 0; mt < 2; mt++)
        #pragma unroll
        for (int nt = 0; nt < 4; nt++)
            #pragma unroll
            for (int i = 0; i < 4; i++) acc[mt][nt][i] = 0.0f;

    // prologue: stages 0,1
    #pragma unroll
    for (int s = 0; s < 2; s++) {
        __half* as = As + s * ASTG16;
        __half* bs = Bs + s * BSTG16;
        const int k0 = s * 32;
        #pragma unroll
        for (int j = 0; j < 2; j++)
            CPA16(smaddr(as + arow * 40 + (ac0 + j) * 8), aSrc + k0 + (ac0 + j) * 8);
        CPA16(smaddr(bs + brow * 40 + bchk * 8), bSrc + k0 + bchk * 8);
        CPCOMMIT();
    }

    const int iters = K >> 5;
    for (int it = 0; it < iters; it++) {
        const int cur = it & 1;
        CPWAIT1();
        __syncthreads();

        const __half* as = As + cur * ASTG16;
        const __half* bs = Bs + cur * BSTG16;
        #pragma unroll
        for (int kk2 = 0; kk2 < 2; kk2++) {
            const int kk = kk2 * 16;
            unsigned af[2][4], bf[4][2];
            #pragma unroll
            for (int mt = 0; mt < 2; mt++) {
                const int rA = (wm * 32 + mt * 16 + g) * 40 + kk + 2 * tg;
                const int rB = (wm * 32 + mt * 16 + 8 + g) * 40 + kk + 2 * tg;
                af[mt][0] = ldh2u(as + rA);
                af[mt][1] = ldh2u(as + rB);
                af[mt][2] = ldh2u(as + rA + 8);
                af[mt][3] = ldh2u(as + rB + 8);
            }
            #pragma unroll
            for (int nt = 0; nt < 4; nt++) {
                const int cb = (wn * 32 + nt * 8 + g) * 40 + kk + 2 * tg;
                bf[nt][0] = ldh2u(bs + cb);
                bf[nt][1] = ldh2u(bs + cb + 8);
            }
            #pragma unroll
            for (int mt = 0; mt < 2; mt++)
                #pragma unroll
                for (int nt = 0; nt < 4; nt++)
                    mma_f16(acc[mt][nt], af[mt], bf[nt]);
        }
        __syncthreads();

        const int k0n = (it + 2) << 5;
        if (k0n < K) {
            __half* asw = As + cur * ASTG16;
            __half* bsw = Bs + cur * BSTG16;
            #pragma unroll
            for (int j = 0; j < 2; j++)
                CPA16(smaddr(asw + arow * 40 + (ac0 + j) * 8), aSrc + k0n + (ac0 + j) * 8);
            CPA16(smaddr(bsw + brow * 40 + bchk * 8), bSrc + k0n + bchk * 8);
        }
        CPCOMMIT();
    }

    #pragma unroll
    for (int mt = 0; mt < 2; mt++) {
        int r0 = m0 + wm * 32 + mt * 16 + g;
        #pragma unroll
        for (int nt = 0; nt < 4; nt++) {
            int c = n0 + wn * 32 + nt * 8 + tg * 2;
            float b0 = bias[c], b1 = bias[c + 1];
            float v0 = acc[mt][nt][0] + b0;
            float v1 = acc[mt][nt][1] + b1;
            float v2 = acc[mt][nt][2] + b0;
            float v3 = acc[mt][nt][3] + b1;
            if (EPI == 1) {
                v0 = gelu_exact(v0); v1 = gelu_exact(v1);
                v2 = gelu_exact(v2); v3 = gelu_exact(v3);
            }
            if (OUTH) {
                __half* C16 = (__half*)Cout;
                *reinterpret_cast<__half2*>(C16 + (size_t)r0 * Nn + c) =
                    __floats2half2_rn(v0, v1);
                *reinterpret_cast<__half2*>(C16 + (size_t)(r0 + 8) * Nn + c) =
                    __floats2half2_rn(v2, v3);
            } else {
                float* Cf = (float*)Cout;
                *reinterpret_cast<float2*>(Cf + (size_t)r0 * Nn + c)       = make_float2(v0, v1);
                *reinterpret_cast<float2*>(Cf + (size_t)(r0 + 8) * Nn + c) = make_float2(v2, v3);
            }
        }
    }
}

// ---------------------------------------------------------------------------
// f16 tensor-core window attention (m16n8k16). qkv f16; softmax fp32;
// V stored transposed [hd][tok] in smem for f16 PV fragments; P staged f16.
// Strides: K tile 40 f16; V^T / P 152 f16 (both conflict-free).
// ---------------------------------------------------------------------------
#define KS16_S 40
#define VT16_S 152
#define SCR16_S 152
#define ATTN_SMEM16 ((NTOK * KS16_S + HD * VT16_S + 4 * 16 * SCR16_S) * 2)  // 40704 B

__global__ void __launch_bounds__(128, 3) attn_f16_kernel(int L) {
    const int win  = blockIdx.x;
    const int head = blockIdx.y;
    const int t    = win >> 4;
    extern __shared__ __half smh[];
    __half* ks  = smh;                        // [144][40]
    __half* vsT = ks + NTOK * KS16_S;         // [32][152]  (V transposed)
    __half* scr = vsT + HD * VT16_S;          // 4 x [16][152]

    const int tid  = threadIdx.x;
    const int lane = tid & 31;
    const int wid  = tid >> 5;
    const int g    = lane >> 2;
    const int tg   = lane & 3;

    const __half* base = g_qkv16 + (size_t)win * NTOK * QKVN;
    const int hc = head * HD;
    for (int idx = tid; idx < NTOK * 4; idx += 128) {
        int row = idx >> 2, c = idx & 3;
        // K: straight copy (16B)
        *reinterpret_cast<uint4*>(&ks[row * KS16_S + c * 8]) =
            *reinterpret_cast<const uint4*>(base + (size_t)row * QKVN + CDIM + hc + c * 8);
        // V: transpose-scatter 8 halves
        uint4 v4 = *reinterpret_cast<const uint4*>(base + (size_t)row * QKVN + 2 * CDIM + hc + c * 8);
        const __half* hv = reinterpret_cast<const __half*>(&v4);
        #pragma unroll
        for (int j = 0; j < 8; j++)
            vsT[(c * 8 + j) * VT16_S + row] = hv[j];
    }
    __syncthreads();

    const float* bmb = g_bm + (((size_t)L * TWIN + t) * NHEAD + head) * NTOK * NTOK;
    __half* wscr = scr + wid * 16 * SCR16_S;
    const float sc = 0.17677669529663687f;   // 1/sqrt(32)

    for (int mt = wid; mt < 9; mt += 4) {
        const int rb = mt * 16;

        // Q fragments straight from gmem (f16 pairs, no cvt)
        const __half* qA = g_qkv16 + (size_t)(win * NTOK + rb + g) * QKVN + hc;
        const __half* qB = g_qkv16 + (size_t)(win * NTOK + rb + 8 + g) * QKVN + hc;
        unsigned aq[2][4];
        #pragma unroll
        for (int kk2 = 0; kk2 < 2; kk2++) {
            const int kk = kk2 * 16 + 2 * tg;
            aq[kk2][0] = ldh2u(qA + kk);
            aq[kk2][1] = ldh2u(qB + kk);
            aq[kk2][2] = ldh2u(qA + kk + 8);
            aq[kk2][3] = ldh2u(qB + kk + 8);
        }

        // S = Q K^T (2 k16-steps) + scale + bias
        float sacc[18][4];
        #pragma unroll
        for (int nt = 0; nt < 18; nt++) {
            sacc[nt][0] = sacc[nt][1] = sacc[nt][2] = sacc[nt][3] = 0.0f;
            const int cb = nt * 8;
            #pragma unroll
            for (int kk2 = 0; kk2 < 2; kk2++) {
                const int ko = (cb + g) * KS16_S + kk2 * 16 + 2 * tg;
                unsigned bf[2];
                bf[0] = ldh2u(ks + ko);
                bf[1] = ldh2u(ks + ko + 8);
                mma_f16(sacc[nt], aq[kk2], bf);
            }
            const float2 bA = *reinterpret_cast<const float2*>(
                bmb + (size_t)(rb + g) * NTOK + cb + tg * 2);
            const float2 bB = *reinterpret_cast<const float2*>(
                bmb + (size_t)(rb + 8 + g) * NTOK + cb + tg * 2);
            sacc[nt][0] = fmaf(sacc[nt][0], sc, bA.x);
            sacc[nt][1] = fmaf(sacc[nt][1], sc, bA.y);
            sacc[nt][2] = fmaf(sacc[nt][2], sc, bB.x);
            sacc[nt][3] = fmaf(sacc[nt][3], sc, bB.y);
        }

        // softmax across the 4-lane quad owning each row pair
        float mxA = -1e30f, mxB = -1e30f;
        #pragma unroll
        for (int nt = 0; nt < 18; nt++) {
            mxA = fmaxf(mxA, fmaxf(sacc[nt][0], sacc[nt][1]));
            mxB = fmaxf(mxB, fmaxf(sacc[nt][2], sacc[nt][3]));
        }
        #pragma unroll
        for (int o = 1; o <= 2; o <<= 1) {
            mxA = fmaxf(mxA, __shfl_xor_sync(0xFFFFFFFFu, mxA, o));
            mxB = fmaxf(mxB, __shfl_xor_sync(0xFFFFFFFFu, mxB, o));
        }
        float smA = 0.0f, smB = 0.0f;
        #pragma unroll
        for (int nt = 0; nt < 18; nt++) {
            sacc[nt][0] = __expf(sacc[nt][0] - mxA);
            sacc[nt][1] = __expf(sacc[nt][1] - mxA);
            sacc[nt][2] = __expf(sacc[nt][2] - mxB);
            sacc[nt][3] = __expf(sacc[nt][3] - mxB);
            smA += sacc[nt][0] + sacc[nt][1];
            smB += sacc[nt][2] + sacc[nt][3];
        }
        #pragma unroll
        for (int o = 1; o <= 2; o <<= 1) {
            smA += __shfl_xor_sync(0xFFFFFFFFu, smA, o);
            smB += __shfl_xor_sync(0xFFFFFFFFu, smB, o);
        }
        const float invA = 1.0f / smA;
        const float invB = 1.0f / smB;

        // stage P (f16) into per-warp scratch
        #pragma unroll
        for (int nt = 0; nt < 18; nt++) {
            const int cc = nt * 8 + tg * 2;
            *reinterpret_cast<__half2*>(&wscr[g * SCR16_S + cc]) =
                __floats2half2_rn(sacc[nt][0], sacc[nt][1]);
            *reinterpret_cast<__half2*>(&wscr[(g + 8) * SCR16_S + cc]) =
                __floats2half2_rn(sacc[nt][2], sacc[nt][3]);
        }
        __syncwarp();

        // O = P V (9 k16-steps, nt=4)
        float oacc[4][4];
        #pragma unroll
        for (int nt = 0; nt < 4; nt++)
            oacc[nt][0] = oacc[nt][1] = oacc[nt][2] = oacc[nt][3] = 0.0f;
        #pragma unroll
        for (int kk = 0; kk < 9; kk++) {
            const int ko = kk * 16 + 2 * tg;
            unsigned ap[4];
            ap[0] = ldh2u(wscr + g * SCR16_S + ko);
            ap[1] = ldh2u(wscr + (g + 8) * SCR16_S + ko);
            ap[2] = ldh2u(wscr + g * SCR16_S + ko + 8);
            ap[3] = ldh2u(wscr + (g + 8) * SCR16_S + ko + 8);
            #pragma unroll
            for (int nt = 0; nt < 4; nt++) {
                const int vo = (nt * 8 + g) * VT16_S + ko;
                unsigned bf[2];
                bf[0] = ldh2u(vsT + vo);
                bf[1] = ldh2u(vsT + vo + 8);
                mma_f16(oacc[nt], ap, bf);
            }
        }
        __syncwarp();

        #pragma unroll
        for (int nt = 0; nt < 4; nt++) {
            const int c = nt * 8 + tg * 2;
            __half* opA = g_ao16 + ((size_t)win * NTOK + rb + g) * CDIM + hc + c;
            __half* opB = g_ao16 + ((size_t)win * NTOK + rb + 8 + g) * CDIM + hc + c;
            *reinterpret_cast<__half2*>(opA) =
                __floats2half2_rn(oacc[nt][0] * invA, oacc[nt][1] * invA);
            *reinterpret_cast<__half2*>(opB) =
                __floats2half2_rn(oacc[nt][2] * invB, oacc[nt][3] * invB);
        }
    }
}

// ---------------------------------------------------------------------------
// LayerNorm + residual: xout[p] = xin[p] + LN(y[r])*g + b; optional f16 copy.
// mode 0: p=r; 1: un-window; 2: un-window + un-roll.  One warp per row.
// ---------------------------------------------------------------------------
__global__ void ln_add_kernel(const float* __restrict__ y,
                              const float* __restrict__ g,
                              const float* __restrict__ b,
                              const float* __restrict__ xin,
                              float* __restrict__ xout,
                              __half* __restrict__ xh16,
                              int mode) {
    int w = (blockIdx.x * blockDim.x + threadIdx.x) >> 5;
    int lane = threadIdx.x & 31;
    if (w >= MTOK) return;
    size_t p;
    if (mode == 0) {
        p = (size_t)w;
    } else {
        int n = w % NTOK, win = w / NTOK;
        int l = win % NWW, t = win / NWW;
        int tz = t / 8, th = t % 8;
        int z1 = n / 72, h1 = (n % 72) / 12, w1 = n % 12;
        int zr = tz * 2 + z1, hr = th * 6 + h1, wr = l * 12 + w1;
        int z, hh, ww;
        if (mode == 2) { z = (zr + 7) & 7; hh = (hr + 45) % 48; ww = (wr + 186) % 192; }
        else           { z = zr; hh = hr; ww = wr; }
        p = ((size_t)z * 48 + hh) * 192 + ww;
    }
    const float* yr = y + (size_t)w * CDIM;
    float v[6];
    float sum = 0.0f;
    #pragma unroll
    for (int i = 0; i < 6; i++) { v[i] = yr[lane + 32 * i]; sum += v[i]; }
    #pragma unroll
    for (int o = 16; o; o >>= 1) sum += __shfl_xor_sync(0xFFFFFFFFu, sum, o);
    float mu = sum * (1.0f / 192.0f);
    float var = 0.0f;
    #pragma unroll
    for (int i = 0; i < 6; i++) { float d = v[i] - mu; var += d * d; }
    #pragma unroll
    for (int o = 16; o; o >>= 1) var += __shfl_xor_sync(0xFFFFFFFFu, var, o);
    var *= (1.0f / 192.0f);
    float rs = rsqrtf(var + 1e-5f);
    const float* xi = xin + p * CDIM;
    float* xo = xout + p * CDIM;
    #pragma unroll
    for (int i = 0; i < 6; i++) {
        int c = lane + 32 * i;
        float val = xi[c] + (v[i] - mu) * rs * g[c] + b[c];
        xo[c] = val;
        if (xh16) xh16[p * CDIM + c] = __float2half_rn(val);
    }
}

extern "C" void kernel_launch(void* const* d_in, const int* in_sizes, int n_in,
                              void* d_out, int out_size) {
    const float* x_in       = (const float*)d_in[0];
    const float* qkv_w      = (const float*)d_in[1];
    const float* qkv_b      = (const float*)d_in[2];
    const float* proj_w     = (const float*)d_in[3];
    const float* proj_b     = (const float*)d_in[4];
    const float* bias_table = (const float*)d_in[5];
    const float* n1_g       = (const float*)d_in[6];
    const float* n1_b       = (const float*)d_in[7];
    const float* n2_g       = (const float*)d_in[8];
    const float* n2_b       = (const float*)d_in[9];
    const float* w1         = (const float*)d_in[10];
    const float* b1         = (const float*)d_in[11];
    const float* w2         = (const float*)d_in[12];
    const float* b2         = (const float*)d_in[13];
    // d_in[14..16] = Z,H,W scalars (fixed 8,48,192)

    float  *gx, *gtmp;
    __half *gxh, *gqkv, *gao, *gh, *gwt;
    cudaGetSymbolAddress((void**)&gx,   g_x);
    cudaGetSymbolAddress((void**)&gtmp, g_tmp);
    cudaGetSymbolAddress((void**)&gxh,  g_xh16);
    cudaGetSymbolAddress((void**)&gqkv, g_qkv16);
    cudaGetSymbolAddress((void**)&gao,  g_ao16);
    cudaGetSymbolAddress((void**)&gh,   g_h16);
    cudaGetSymbolAddress((void**)&gwt,  g_wt16);

    cudaFuncSetAttribute(hgemm_kernel<0,1,1>, cudaFuncAttributeMaxDynamicSharedMemorySize, GEMM_SMEM16);
    cudaFuncSetAttribute(hgemm_kernel<0,0,0>, cudaFuncAttributeMaxDynamicSharedMemorySize, GEMM_SMEM16);
    cudaFuncSetAttribute(hgemm_kernel<1,0,1>, cudaFuncAttributeMaxDynamicSharedMemorySize, GEMM_SMEM16);
    cudaFuncSetAttribute(attn_f16_kernel, cudaFuncAttributeMaxDynamicSharedMemorySize, ATTN_SMEM16);

    // prep: transpose+cvt weights to f16 [N][K]; cvt x_in to f16; bias table
    dim3 tb(32, 8);
    for (int L = 0; L < 2; L++) {
        transpose_cvt_kernel<<<dim3(QKVN / 32, CDIM / 32), tb>>>(
            qkv_w + (size_t)L * CDIM * QKVN, gwt + WQ_OFF + (size_t)L * CDIM * QKVN, CDIM, QKVN);
        transpose_cvt_kernel<<<dim3(CDIM / 32, CDIM / 32), tb>>>(
            proj_w + (size_t)L * CDIM * CDIM, gwt + WP_OFF + (size_t)L * CDIM * CDIM, CDIM, CDIM);
        transpose_cvt_kernel<<<dim3(FFN / 32, CDIM / 32), tb>>>(
            w1 + (size_t)L * CDIM * FFN, gwt + W1_OFF + (size_t)L * CDIM * FFN, CDIM, FFN);
        transpose_cvt_kernel<<<dim3(CDIM / 32, FFN / 32), tb>>>(
            w2 + (size_t)L * FFN * CDIM, gwt + W2_OFF + (size_t)L * FFN * CDIM, FFN, CDIM);
    }
    cvt_f16_kernel<<<(MTOK * CDIM + 255) / 256, 256>>>(x_in, gxh, MTOK * CDIM);
    {
        size_t total = (size_t)2 * TWIN * NHEAD * NTOK * NTOK;
        biasmask_kernel<<<(unsigned)((total + 255) / 256), 256>>>(bias_table);
    }

    for (int L = 0; L < 2; L++) {
        const float* xsrc = (L == 0) ? x_in : gx;

        // QKV (fused window gather), f16 out
        hgemm_kernel<0,1,1><<<dim3(QKVN / 64, MTOK / 128), 256, GEMM_SMEM16>>>(
            gxh, gwt + WQ_OFF + (size_t)L * CDIM * QKVN, qkv_b + (size_t)L * QKVN,
            gqkv, CDIM, QKVN, L);

        attn_f16_kernel<<<dim3(NWIN, NHEAD), 128, ATTN_SMEM16>>>(L);

        // proj: f16 in, fp32 out
        hgemm_kernel<0,0,0><<<dim3(CDIM / 64, MTOK / 128), 256, GEMM_SMEM16>>>(
            gao, gwt + WP_OFF + (size_t)L * CDIM * CDIM, proj_b + (size_t)L * CDIM,
            gtmp, CDIM, CDIM, 0);

        // x = xsrc + LN(un-window(proj_out));  + f16 copy for next GEMM
        ln_add_kernel<<<(MTOK * 32 + 255) / 256, 256>>>(
            gtmp, n1_g + (size_t)L * CDIM, n1_b + (size_t)L * CDIM,
            xsrc, gx, gxh, L ? 2 : 1);

        // MLP up: gelu, f16 out
        hgemm_kernel<1,0,1><<<dim3(FFN / 64, MTOK / 128), 256, GEMM_SMEM16>>>(
            gxh, gwt + W1_OFF + (size_t)L * CDIM * FFN, b1 + (size_t)L * FFN,
            gh, CDIM, FFN, 0);

        // MLP down: f16 in, fp32 out
        hgemm_kernel<0,0,0><<<dim3(CDIM / 64, MTOK / 128), 256, GEMM_SMEM16>>>(
            gh, gwt + W2_OFF + (size_t)L * FFN * CDIM, b2 + (size_t)L * CDIM,
            gtmp, FFN, CDIM, 0);

        // x = x + LN(mlp_out); final layer writes straight to d_out (fp32 only)
        float*  xo  = (L == 1) ? (float*)d_out : gx;
        __half* xho = (L == 1) ? (__half*)nullptr : gxh;
        ln_add_kernel<<<(MTOK * 32 + 255) / 256, 256>>>(
            gtmp, n2_g + (size_t)L * CDIM, n2_b + (size_t)L * CDIM,
            gx, xo, xho, 0);
    }
}

// round 10
// speedup vs baseline: 1.8091x; 1.0627x over previous
#include <cuda_runtime.h>
#include <cuda_fp16.h>
#include <math.h>

#define MTOK   73728
#define CDIM   192
#define NHEAD  6
#define HD     32
#define NTOK   144
#define NWIN   512
#define TWIN   32
#define NWW    16
#define NB     3312
#define QKVN   576
#define FFN    768

// fp32 buffers (residual stream, LN temp, bias table)
__device__ float  g_x   [(size_t)MTOK * CDIM];
__device__ float  g_tmp [(size_t)MTOK * CDIM];
__device__ float  g_bm  [(size_t)2 * TWIN * NHEAD * NTOK * NTOK];
// f16 activation buffers
__device__ __half g_xh16 [(size_t)MTOK * CDIM];
__device__ __half g_qkv16[(size_t)MTOK * QKVN];
__device__ __half g_ao16 [(size_t)MTOK * CDIM];
__device__ __half g_h16  [(size_t)MTOK * FFN];
// f16 transposed weights [N][K]: qkv | proj | w1 | w2 (both layers)
#define WQ_OFF 0
#define WP_OFF 221184
#define W1_OFF 294912
#define W2_OFF 589824
__device__ __half g_wt16[884736];

// ---------------------------------------------------------------------------
// helpers
// ---------------------------------------------------------------------------
__device__ __forceinline__ void mma_f16(float* d, const unsigned* a, const unsigned* b) {
    asm volatile(
        "mma.sync.aligned.m16n8k16.row.col.f32.f16.f16.f32 "
        "{%0,%1,%2,%3}, {%4,%5,%6,%7}, {%8,%9}, {%0,%1,%2,%3};\n"
        : "+f"(d[0]), "+f"(d[1]), "+f"(d[2]), "+f"(d[3])
        : "r"(a[0]), "r"(a[1]), "r"(a[2]), "r"(a[3]),
          "r"(b[0]), "r"(b[1]));
}

__device__ __forceinline__ void ldsm_x4(unsigned& r0, unsigned& r1,
                                        unsigned& r2, unsigned& r3, unsigned a) {
    asm volatile("ldmatrix.sync.aligned.m8n8.x4.shared.b16 {%0,%1,%2,%3}, [%4];"
                 : "=r"(r0), "=r"(r1), "=r"(r2), "=r"(r3) : "r"(a));
}
#define STSM_X2(addr, r0, r1) \
    asm volatile("stmatrix.sync.aligned.m8n8.x2.shared.b16 [%0], {%1,%2};" \
                 :: "r"(addr), "r"(r0), "r"(r1))

__device__ __forceinline__ unsigned h2u(float a, float b) {
    __half2 h = __floats2half2_rn(a, b);
    return reinterpret_cast<unsigned&>(h);
}

__device__ __forceinline__ unsigned smaddr(const void* p) {
    return (unsigned)__cvta_generic_to_shared(p);
}
#define CPA16(dst, src) asm volatile("cp.async.cg.shared.global [%0], [%1], 16;" :: "r"(dst), "l"(src))
#define CPCOMMIT()      asm volatile("cp.async.commit_group;")
#define CPWAIT1()       asm volatile("cp.async.wait_group 1;")

__device__ __forceinline__ float gelu_exact(float v) {
    return 0.5f * v * (1.0f + erff(v * 0.70710678118654752f));
}

// ---------------------------------------------------------------------------
// Prep: tiled transpose + cvt fp32 [K][N] -> f16 [N][K]
// ---------------------------------------------------------------------------
__global__ void transpose_cvt_kernel(const float* __restrict__ src,
                                     __half* __restrict__ dst, int K, int N) {
    __shared__ float t[32][33];
    const int n0 = blockIdx.x * 32, k0 = blockIdx.y * 32;
    const int tx = threadIdx.x, ty = threadIdx.y;   // 32 x 8
    #pragma unroll
    for (int i = 0; i < 32; i += 8)
        t[ty + i][tx] = src[(size_t)(k0 + ty + i) * N + n0 + tx];
    __syncthreads();
    #pragma unroll
    for (int i = 0; i < 32; i += 8)
        dst[(size_t)(n0 + ty + i) * K + k0 + tx] = __float2half_rn(t[tx][ty + i]);
}

__global__ void cvt_f16_kernel(const float* __restrict__ src,
                               __half* __restrict__ dst, int n) {
    int i = blockIdx.x * blockDim.x + threadIdx.x;
    if (i < n) dst[i] = __float2half_rn(src[i]);
}

// ---------------------------------------------------------------------------
// Dense (relative-position bias + shift mask)
// ---------------------------------------------------------------------------
__global__ void biasmask_kernel(const float* __restrict__ table) {
    size_t idx = (size_t)blockIdx.x * blockDim.x + threadIdx.x;
    size_t total = (size_t)2 * TWIN * NHEAD * NTOK * NTOK;
    if (idx >= total) return;
    int m = idx % NTOK; size_t r = idx / NTOK;
    int n = r % NTOK;   r /= NTOK;
    int head = r % NHEAD; r /= NHEAD;
    int t = r % TWIN;   int L = (int)(r / TWIN);
    int z1 = n / 72, h1 = (n % 72) / 12, w1 = n % 12;
    int z2 = m / 72, h2 = (m % 72) / 12, w2 = m % 12;
    int pos = 828 * (z1 + 2 * z2) + 23 * (h1 + 6 * h2) + (w1 - w2 + 11);
    float v = table[(((size_t)L * NB + pos) * TWIN + t) * NHEAD + head];
    if (L == 1) {
        int tz = t / 8, th = t % 8;
        int idn = (((tz * 2 + z1) >= 1) ? 2 : 0) + (((th * 6 + h1) >= 3) ? 1 : 0);
        int idm = (((tz * 2 + z2) >= 1) ? 2 : 0) + (((th * 6 + h2) >= 3) ? 1 : 0);
        if (idn != idm) v += -10000.0f;
    }
    g_bm[idx] = v;
}

// ---------------------------------------------------------------------------
// f16 GEMM (m16n8k16, fp32 accum) with ldmatrix fragment loads.
// BM=128, BN=64, BK=32, 256 thr / 8 warps (4m x 2n), warp tile 32x32.
// Per k16-step: 4 LDSM.x4 + 8 mma (was 16 LDS.32 + 8 mma).
// A f16 [M][K]; B f16 [N][K]. 2-stage cp.async. Stride 40 f16 = LDSM
// conflict-free (row starts 20r mod 32 pairwise-disjoint bank quads).
// ---------------------------------------------------------------------------
#define ASTG16 (128 * 40)
#define BSTG16 (64 * 40)
#define GEMM_SMEM16 ((2 * ASTG16 + 2 * BSTG16) * 2)   // 30720 B

template <int EPI, int GATHER, int OUTH>
__global__ void __launch_bounds__(256, 3)
hgemm_kernel(const __half* __restrict__ A,
             const __half* __restrict__ B,
             const float* __restrict__ bias,
             void* __restrict__ Cout,
             int K, int Nn, int rolled) {
    extern __shared__ __half hsm[];
    __half* As = hsm;
    __half* Bs = hsm + 2 * ASTG16;

    const int tid  = threadIdx.x;
    const int lane = tid & 31;
    const int wid  = tid >> 5;
    const int wm   = wid >> 1;          // 0..3
    const int wn   = wid & 1;           // 0..1
    const int g    = lane >> 2;
    const int tg   = lane & 3;
    const int m0   = blockIdx.y * 128;
    const int n0   = blockIdx.x * 64;

    // ldmatrix per-lane byte offsets
    const unsigned lrow = lane & 7;
    const unsigned lsel = (lane >> 3) & 1;
    const unsigned lhi  = lane >> 4;
    // A x4: m0 rows+0..7@k, m1 rows+8..15@k, m2 rows+0..7@k+8, m3 rows+8..15@k+8
    const unsigned aoff = ((lrow + lsel * 8) * 40 + lhi * 8) * 2;
    // B x4: m0 rows+0..7@k, m1 rows+0..7@k+8, m2 rows+8..15@k, m3 rows+8..15@k+8
    const unsigned boff = ((lrow + lhi * 8) * 40 + lsel * 8) * 2;

    // copy roles: A row = tid>>1, 2 x 16B chunks; B row = tid>>2, 1 x 16B
    const int arow = tid >> 1;
    const int ac0  = (tid & 1) * 2;
    const int brow = tid >> 2;
    const int bchk = tid & 3;

    size_t arowp;
    {
        int r = m0 + arow;
        if (GATHER) {
            int n = r % NTOK, win = r / NTOK;
            int l = win % NWW, t = win / NWW;
            int tz = t / 8, th = t % 8;
            int z1 = n / 72, h1 = (n % 72) / 12, w1 = n % 12;
            int zr = tz * 2 + z1, hr = th * 6 + h1, wr = l * 12 + w1;
            int z, hh, ww;
            if (rolled) { z = (zr + 7) & 7; hh = (hr + 45) % 48; ww = (wr + 186) % 192; }
            else        { z = zr; hh = hr; ww = wr; }
            arowp = ((size_t)z * 48 + hh) * 192 + ww;
        } else {
            arowp = (size_t)r;
        }
    }
    const __half* aSrc = A + arowp * K;
    const __half* bSrc = B + (size_t)(n0 + brow) * K;

    float acc[2][4][4];
    #pragma unroll
    for (int mt = 0; mt < 2; mt++)
        #pragma unroll
        for (int nt = 0; nt < 4; nt++)
            #pragma unroll
            for (int i = 0; i < 4; i++) acc[mt][nt][i] = 0.0f;

    // prologue: stages 0,1
    #pragma unroll
    for (int s = 0; s < 2; s++) {
        __half* as = As + s * ASTG16;
        __half* bs = Bs + s * BSTG16;
        const int k0 = s * 32;
        #pragma unroll
        for (int j = 0; j < 2; j++)
            CPA16(smaddr(as + arow * 40 + (ac0 + j) * 8), aSrc + k0 + (ac0 + j) * 8);
        CPA16(smaddr(bs + brow * 40 + bchk * 8), bSrc + k0 + bchk * 8);
        CPCOMMIT();
    }

    const int iters = K >> 5;
    for (int it = 0; it < iters; it++) {
        const int cur = it & 1;
        CPWAIT1();
        __syncthreads();

        const __half* as = As + cur * ASTG16;
        const __half* bs = Bs + cur * BSTG16;
        const unsigned aB = smaddr(as) + (unsigned)(wm * 32 * 40) * 2 + aoff;
        const unsigned bB = smaddr(bs) + (unsigned)(wn * 32 * 40) * 2 + boff;
        #pragma unroll
        for (int kk2 = 0; kk2 < 2; kk2++) {
            unsigned af[2][4], bf[4][2];
            ldsm_x4(af[0][0], af[0][1], af[0][2], af[0][3], aB + kk2 * 32);
            ldsm_x4(af[1][0], af[1][1], af[1][2], af[1][3], aB + 1280 + kk2 * 32);
            ldsm_x4(bf[0][0], bf[0][1], bf[1][0], bf[1][1], bB + kk2 * 32);
            ldsm_x4(bf[2][0], bf[2][1], bf[3][0], bf[3][1], bB + 1280 + kk2 * 32);
            #pragma unroll
            for (int mt = 0; mt < 2; mt++)
                #pragma unroll
                for (int nt = 0; nt < 4; nt++)
                    mma_f16(acc[mt][nt], af[mt], bf[nt]);
        }
        __syncthreads();

        const int k0n = (it + 2) << 5;
        if (k0n < K) {
            __half* asw = As + cur * ASTG16;
            __half* bsw = Bs + cur * BSTG16;
            #pragma unroll
            for (int j = 0; j < 2; j++)
                CPA16(smaddr(asw + arow * 40 + (ac0 + j) * 8), aSrc + k0n + (ac0 + j) * 8);
            CPA16(smaddr(bsw + brow * 40 + bchk * 8), bSrc + k0n + bchk * 8);
        }
        CPCOMMIT();
    }

    #pragma unroll
    for (int mt = 0; mt < 2; mt++) {
        int r0 = m0 + wm * 32 + mt * 16 + g;
        #pragma unroll
        for (int nt = 0; nt < 4; nt++) {
            int c = n0 + wn * 32 + nt * 8 + tg * 2;
            float b0 = bias[c], b1 = bias[c + 1];
            float v0 = acc[mt][nt][0] + b0;
            float v1 = acc[mt][nt][1] + b1;
            float v2 = acc[mt][nt][2] + b0;
            float v3 = acc[mt][nt][3] + b1;
            if (EPI == 1) {
                v0 = gelu_exact(v0); v1 = gelu_exact(v1);
                v2 = gelu_exact(v2); v3 = gelu_exact(v3);
            }
            if (OUTH) {
                __half* C16 = (__half*)Cout;
                *reinterpret_cast<__half2*>(C16 + (size_t)r0 * Nn + c) =
                    __floats2half2_rn(v0, v1);
                *reinterpret_cast<__half2*>(C16 + (size_t)(r0 + 8) * Nn + c) =
                    __floats2half2_rn(v2, v3);
            } else {
                float* Cf = (float*)Cout;
                *reinterpret_cast<float2*>(Cf + (size_t)r0 * Nn + c)       = make_float2(v0, v1);
                *reinterpret_cast<float2*>(Cf + (size_t)(r0 + 8) * Nn + c) = make_float2(v2, v3);
            }
        }
    }
}

// ---------------------------------------------------------------------------
// f16 tensor-core window attention with ldmatrix/stmatrix fragment movement.
// K tile stride 40; V^T / P scratch stride 152 (both LDSM conflict-free).
// ---------------------------------------------------------------------------
#define KS16_S 40
#define VT16_S 152
#define SCR16_S 152
#define ATTN_SMEM16 ((NTOK * KS16_S + HD * VT16_S + 4 * 16 * SCR16_S) * 2)  // 40704 B

__global__ void __launch_bounds__(128, 3) attn_f16_kernel(int L) {
    const int win  = blockIdx.x;
    const int head = blockIdx.y;
    const int t    = win >> 4;
    extern __shared__ __half smh[];
    __half* ks  = smh;                        // [144][40]
    __half* vsT = ks + NTOK * KS16_S;         // [32][152]  (V transposed)
    __half* scr = vsT + HD * VT16_S;          // 4 x [16][152]

    const int tid  = threadIdx.x;
    const int lane = tid & 31;
    const int wid  = tid >> 5;
    const int g    = lane >> 2;
    const int tg   = lane & 3;

    const unsigned lrow = lane & 7;
    const unsigned lsel = (lane >> 3) & 1;
    const unsigned lhi  = lane >> 4;
    const unsigned kboff = ((lrow + lhi * 8) * KS16_S + lsel * 8) * 2;   // B-style
    const unsigned paoff = ((lrow + lsel * 8) * SCR16_S + lhi * 8) * 2;  // A-style
    const unsigned vboff = ((lrow + lhi * 8) * VT16_S + lsel * 8) * 2;   // B-style

    const __half* base = g_qkv16 + (size_t)win * NTOK * QKVN;
    const int hc = head * HD;
    for (int idx = tid; idx < NTOK * 4; idx += 128) {
        int row = idx >> 2, c = idx & 3;
        *reinterpret_cast<uint4*>(&ks[row * KS16_S + c * 8]) =
            *reinterpret_cast<const uint4*>(base + (size_t)row * QKVN + CDIM + hc + c * 8);
        uint4 v4 = *reinterpret_cast<const uint4*>(base + (size_t)row * QKVN + 2 * CDIM + hc + c * 8);
        const __half* hv = reinterpret_cast<const __half*>(&v4);
        #pragma unroll
        for (int j = 0; j < 8; j++)
            vsT[(c * 8 + j) * VT16_S + row] = hv[j];
    }
    __syncthreads();

    const float* bmb = g_bm + (((size_t)L * TWIN + t) * NHEAD + head) * NTOK * NTOK;
    __half* wscr = scr + wid * 16 * SCR16_S;
    const unsigned kbase  = smaddr(ks) + kboff;
    const unsigned pbase  = smaddr(wscr) + paoff;
    const unsigned vbase  = smaddr(vsT) + vboff;
    const unsigned stbase = smaddr(wscr) + (unsigned)((lane & 15) * SCR16_S) * 2;
    const float sc = 0.17677669529663687f;   // 1/sqrt(32)

    for (int mt = wid; mt < 9; mt += 4) {
        const int rb = mt * 16;

        // Q fragments straight from gmem (f16 pairs, no cvt)
        const __half* qA = g_qkv16 + (size_t)(win * NTOK + rb + g) * QKVN + hc;
        const __half* qB = g_qkv16 + (size_t)(win * NTOK + rb + 8 + g) * QKVN + hc;
        unsigned aq[2][4];
        #pragma unroll
        for (int kk2 = 0; kk2 < 2; kk2++) {
            const int kk = kk2 * 16 + 2 * tg;
            aq[kk2][0] = *reinterpret_cast<const unsigned*>(qA + kk);
            aq[kk2][1] = *reinterpret_cast<const unsigned*>(qB + kk);
            aq[kk2][2] = *reinterpret_cast<const unsigned*>(qA + kk + 8);
            aq[kk2][3] = *reinterpret_cast<const unsigned*>(qB + kk + 8);
        }

        // S = Q K^T (ldmatrix K fragments, nt pairs) + scale + bias
        float sacc[18][4];
        #pragma unroll
        for (int ntp = 0; ntp < 9; ntp++) {
            float* s0 = sacc[2 * ntp];
            float* s1 = sacc[2 * ntp + 1];
            #pragma unroll
            for (int i = 0; i < 4; i++) { s0[i] = 0.0f; s1[i] = 0.0f; }
            #pragma unroll
            for (int kk2 = 0; kk2 < 2; kk2++) {
                unsigned b0, b1, b2, b3;
                ldsm_x4(b0, b1, b2, b3, kbase + ntp * (16 * KS16_S * 2) + kk2 * 32);
                unsigned bfa[2] = {b0, b1}, bfb[2] = {b2, b3};
                mma_f16(s0, aq[kk2], bfa);
                mma_f16(s1, aq[kk2], bfb);
            }
            #pragma unroll
            for (int h = 0; h < 2; h++) {
                float* sv = h ? s1 : s0;
                const int cb = (2 * ntp + h) * 8;
                const float2 bA = *reinterpret_cast<const float2*>(
                    bmb + (size_t)(rb + g) * NTOK + cb + tg * 2);
                const float2 bB = *reinterpret_cast<const float2*>(
                    bmb + (size_t)(rb + 8 + g) * NTOK + cb + tg * 2);
                sv[0] = fmaf(sv[0], sc, bA.x);
                sv[1] = fmaf(sv[1], sc, bA.y);
                sv[2] = fmaf(sv[2], sc, bB.x);
                sv[3] = fmaf(sv[3], sc, bB.y);
            }
        }

        // softmax across the 4-lane quad owning each row pair
        float mxA = -1e30f, mxB = -1e30f;
        #pragma unroll
        for (int nt = 0; nt < 18; nt++) {
            mxA = fmaxf(mxA, fmaxf(sacc[nt][0], sacc[nt][1]));
            mxB = fmaxf(mxB, fmaxf(sacc[nt][2], sacc[nt][3]));
        }
        #pragma unroll
        for (int o = 1; o <= 2; o <<= 1) {
            mxA = fmaxf(mxA, __shfl_xor_sync(0xFFFFFFFFu, mxA, o));
            mxB = fmaxf(mxB, __shfl_xor_sync(0xFFFFFFFFu, mxB, o));
        }
        float smA = 0.0f, smB = 0.0f;
        #pragma unroll
        for (int nt = 0; nt < 18; nt++) {
            sacc[nt][0] = __expf(sacc[nt][0] - mxA);
            sacc[nt][1] = __expf(sacc[nt][1] - mxA);
            sacc[nt][2] = __expf(sacc[nt][2] - mxB);
            sacc[nt][3] = __expf(sacc[nt][3] - mxB);
            smA += sacc[nt][0] + sacc[nt][1];
            smB += sacc[nt][2] + sacc[nt][3];
        }
        #pragma unroll
        for (int o = 1; o <= 2; o <<= 1) {
            smA += __shfl_xor_sync(0xFFFFFFFFu, smA, o);
            smB += __shfl_xor_sync(0xFFFFFFFFu, smB, o);
        }
        const float invA = 1.0f / smA;
        const float invB = 1.0f / smB;

        // stage P (f16) via stmatrix.x2 (C-fragment layout -> 16x8 tiles)
        #pragma unroll
        for (int nt = 0; nt < 18; nt++) {
            unsigned r0 = h2u(sacc[nt][0], sacc[nt][1]);
            unsigned r1 = h2u(sacc[nt][2], sacc[nt][3]);
            STSM_X2(stbase + nt * 16, r0, r1);
        }
        __syncwarp();

        // O = P V (ldmatrix P + V fragments; 9 k16-steps, nt=4)
        float oacc[4][4];
        #pragma unroll
        for (int nt = 0; nt < 4; nt++)
            oacc[nt][0] = oacc[nt][1] = oacc[nt][2] = oacc[nt][3] = 0.0f;
        #pragma unroll
        for (int kk = 0; kk < 9; kk++) {
            unsigned ap[4];
            ldsm_x4(ap[0], ap[1], ap[2], ap[3], pbase + kk * 32);
            unsigned b0, b1, b2, b3, c0, c1, c2, c3;
            ldsm_x4(b0, b1, b2, b3, vbase + kk * 32);
            ldsm_x4(c0, c1, c2, c3, vbase + (16 * VT16_S * 2) + kk * 32);
            { unsigned bf[2] = {b0, b1}; mma_f16(oacc[0], ap, bf); }
            { unsigned bf[2] = {b2, b3}; mma_f16(oacc[1], ap, bf); }
            { unsigned bf[2] = {c0, c1}; mma_f16(oacc[2], ap, bf); }
            { unsigned bf[2] = {c2, c3}; mma_f16(oacc[3], ap, bf); }
        }
        __syncwarp();

        #pragma unroll
        for (int nt = 0; nt < 4; nt++) {
            const int c = nt * 8 + tg * 2;
            __half* opA = g_ao16 + ((size_t)win * NTOK + rb + g) * CDIM + hc + c;
            __half* opB = g_ao16 + ((size_t)win * NTOK + rb + 8 + g) * CDIM + hc + c;
            *reinterpret_cast<__half2*>(opA) =
                __floats2half2_rn(oacc[nt][0] * invA, oacc[nt][1] * invA);
            *reinterpret_cast<__half2*>(opB) =
                __floats2half2_rn(oacc[nt][2] * invB, oacc[nt][3] * invB);
        }
    }
}

// ---------------------------------------------------------------------------
// LayerNorm + residual: xout[p] = xin[p] + LN(y[r])*g + b; optional f16 copy.
// mode 0: p=r; 1: un-window; 2: un-window + un-roll.  One warp per row.
// ---------------------------------------------------------------------------
__global__ void ln_add_kernel(const float* __restrict__ y,
                              const float* __restrict__ g,
                              const float* __restrict__ b,
                              const float* __restrict__ xin,
                              float* __restrict__ xout,
                              __half* __restrict__ xh16,
                              int mode) {
    int w = (blockIdx.x * blockDim.x + threadIdx.x) >> 5;
    int lane = threadIdx.x & 31;
    if (w >= MTOK) return;
    size_t p;
    if (mode == 0) {
        p = (size_t)w;
    } else {
        int n = w % NTOK, win = w / NTOK;
        int l = win % NWW, t = win / NWW;
        int tz = t / 8, th = t % 8;
        int z1 = n / 72, h1 = (n % 72) / 12, w1 = n % 12;
        int zr = tz * 2 + z1, hr = th * 6 + h1, wr = l * 12 + w1;
        int z, hh, ww;
        if (mode == 2) { z = (zr + 7) & 7; hh = (hr + 45) % 48; ww = (wr + 186) % 192; }
        else           { z = zr; hh = hr; ww = wr; }
        p = ((size_t)z * 48 + hh) * 192 + ww;
    }
    const float* yr = y + (size_t)w * CDIM;
    float v[6];
    float sum = 0.0f;
    #pragma unroll
    for (int i = 0; i < 6; i++) { v[i] = yr[lane + 32 * i]; sum += v[i]; }
    #pragma unroll
    for (int o = 16; o; o >>= 1) sum += __shfl_xor_sync(0xFFFFFFFFu, sum, o);
    float mu = sum * (1.0f / 192.0f);
    float var = 0.0f;
    #pragma unroll
    for (int i = 0; i < 6; i++) { float d = v[i] - mu; var += d * d; }
    #pragma unroll
    for (int o = 16; o; o >>= 1) var += __shfl_xor_sync(0xFFFFFFFFu, var, o);
    var *= (1.0f / 192.0f);
    float rs = rsqrtf(var + 1e-5f);
    const float* xi = xin + p * CDIM;
    float* xo = xout + p * CDIM;
    #pragma unroll
    for (int i = 0; i < 6; i++) {
        int c = lane + 32 * i;
        float val = xi[c] + (v[i] - mu) * rs * g[c] + b[c];
        xo[c] = val;
        if (xh16) xh16[p * CDIM + c] = __float2half_rn(val);
    }
}

extern "C" void kernel_launch(void* const* d_in, const int* in_sizes, int n_in,
                              void* d_out, int out_size) {
    const float* x_in       = (const float*)d_in[0];
    const float* qkv_w      = (const float*)d_in[1];
    const float* qkv_b      = (const float*)d_in[2];
    const float* proj_w     = (const float*)d_in[3];
    const float* proj_b     = (const float*)d_in[4];
    const float* bias_table = (const float*)d_in[5];
    const float* n1_g       = (const float*)d_in[6];
    const float* n1_b       = (const float*)d_in[7];
    const float* n2_g       = (const float*)d_in[8];
    const float* n2_b       = (const float*)d_in[9];
    const float* w1         = (const float*)d_in[10];
    const float* b1         = (const float*)d_in[11];
    const float* w2         = (const float*)d_in[12];
    const float* b2         = (const float*)d_in[13];
    // d_in[14..16] = Z,H,W scalars (fixed 8,48,192)

    float  *gx, *gtmp;
    __half *gxh, *gqkv, *gao, *gh, *gwt;
    cudaGetSymbolAddress((void**)&gx,   g_x);
    cudaGetSymbolAddress((void**)&gtmp, g_tmp);
    cudaGetSymbolAddress((void**)&gxh,  g_xh16);
    cudaGetSymbolAddress((void**)&gqkv, g_qkv16);
    cudaGetSymbolAddress((void**)&gao,  g_ao16);
    cudaGetSymbolAddress((void**)&gh,   g_h16);
    cudaGetSymbolAddress((void**)&gwt,  g_wt16);

    cudaFuncSetAttribute(hgemm_kernel<0,1,1>, cudaFuncAttributeMaxDynamicSharedMemorySize, GEMM_SMEM16);
    cudaFuncSetAttribute(hgemm_kernel<0,0,0>, cudaFuncAttributeMaxDynamicSharedMemorySize, GEMM_SMEM16);
    cudaFuncSetAttribute(hgemm_kernel<1,0,1>, cudaFuncAttributeMaxDynamicSharedMemorySize, GEMM_SMEM16);
    cudaFuncSetAttribute(attn_f16_kernel, cudaFuncAttributeMaxDynamicSharedMemorySize, ATTN_SMEM16);

    // prep: transpose+cvt weights to f16 [N][K]; cvt x_in to f16; bias table
    dim3 tb(32, 8);
    for (int L = 0; L < 2; L++) {
        transpose_cvt_kernel<<<dim3(QKVN / 32, CDIM / 32), tb>>>(
            qkv_w + (size_t)L * CDIM * QKVN, gwt + WQ_OFF + (size_t)L * CDIM * QKVN, CDIM, QKVN);
        transpose_cvt_kernel<<<dim3(CDIM / 32, CDIM / 32), tb>>>(
            proj_w + (size_t)L * CDIM * CDIM, gwt + WP_OFF + (size_t)L * CDIM * CDIM, CDIM, CDIM);
        transpose_cvt_kernel<<<dim3(FFN / 32, CDIM / 32), tb>>>(
            w1 + (size_t)L * CDIM * FFN, gwt + W1_OFF + (size_t)L * CDIM * FFN, CDIM, FFN);
        transpose_cvt_kernel<<<dim3(CDIM / 32, FFN / 32), tb>>>(
            w2 + (size_t)L * FFN * CDIM, gwt + W2_OFF + (size_t)L * FFN * CDIM, FFN, CDIM);
    }
    cvt_f16_kernel<<<(MTOK * CDIM + 255) / 256, 256>>>(x_in, gxh, MTOK * CDIM);
    {
        size_t total = (size_t)2 * TWIN * NHEAD * NTOK * NTOK;
        biasmask_kernel<<<(unsigned)((total + 255) / 256), 256>>>(bias_table);
    }

    for (int L = 0; L < 2; L++) {
        const float* xsrc = (L == 0) ? x_in : gx;

        // QKV (fused window gather), f16 out
        hgemm_kernel<0,1,1><<<dim3(QKVN / 64, MTOK / 128), 256, GEMM_SMEM16>>>(
            gxh, gwt + WQ_OFF + (size_t)L * CDIM * QKVN, qkv_b + (size_t)L * QKVN,
            gqkv, CDIM, QKVN, L);

        attn_f16_kernel<<<dim3(NWIN, NHEAD), 128, ATTN_SMEM16>>>(L);

        // proj: f16 in, fp32 out
        hgemm_kernel<0,0,0><<<dim3(CDIM / 64, MTOK / 128), 256, GEMM_SMEM16>>>(
            gao, gwt + WP_OFF + (size_t)L * CDIM * CDIM, proj_b + (size_t)L * CDIM,
            gtmp, CDIM, CDIM, 0);

        // x = xsrc + LN(un-window(proj_out));  + f16 copy for next GEMM
        ln_add_kernel<<<(MTOK * 32 + 255) / 256, 256>>>(
            gtmp, n1_g + (size_t)L * CDIM, n1_b + (size_t)L * CDIM,
            xsrc, gx, gxh, L ? 2 : 1);

        // MLP up: gelu, f16 out
        hgemm_kernel<1,0,1><<<dim3(FFN / 64, MTOK / 128), 256, GEMM_SMEM16>>>(
            gxh, gwt + W1_OFF + (size_t)L * CDIM * FFN, b1 + (size_t)L * FFN,
            gh, CDIM, FFN, 0);

        // MLP down: f16 in, fp32 out
        hgemm_kernel<0,0,0><<<dim3(CDIM / 64, MTOK / 128), 256, GEMM_SMEM16>>>(
            gh, gwt + W2_OFF + (size_t)L * FFN * CDIM, b2 + (size_t)L * CDIM,
            gtmp, FFN, CDIM, 0);

        // x = x + LN(mlp_out); final layer writes straight to d_out (fp32 only)
        float*  xo  = (L == 1) ? (float*)d_out : gx;
        __half* xho = (L == 1) ? (__half*)nullptr : gxh;
        ln_add_kernel<<<(MTOK * 32 + 255) / 256, 256>>>(
            gtmp, n2_g + (size_t)L * CDIM, n2_b + (size_t)L * CDIM,
            gx, xo, xho, 0);
    }
}

// round 11
// speedup vs baseline: 1.8999x; 1.0501x over previous
#include <cuda_runtime.h>
#include <cuda_fp16.h>
#include <math.h>

#define MTOK   73728
#define CDIM   192
#define NHEAD  6
#define HD     32
#define NTOK   144
#define NWIN   512
#define TWIN   32
#define NWW    16
#define NB     3312
#define QKVN   576
#define FFN    768

// fp32 buffers (residual stream, LN temp, bias table)
__device__ float  g_x   [(size_t)MTOK * CDIM];
__device__ float  g_tmp [(size_t)MTOK * CDIM];
__device__ float  g_bm  [(size_t)2 * TWIN * NHEAD * NTOK * NTOK];
// f16 activation buffers
__device__ __half g_xh16 [(size_t)MTOK * CDIM];
__device__ __half g_qkv16[(size_t)MTOK * QKVN];
__device__ __half g_ao16 [(size_t)MTOK * CDIM];
__device__ __half g_h16  [(size_t)MTOK * FFN];
// f16 transposed weights [N][K]: qkv | proj | w1 | w2 (both layers)
#define WQ_OFF 0
#define WP_OFF 221184
#define W1_OFF 294912
#define W2_OFF 589824
__device__ __half g_wt16[884736];

// ---------------------------------------------------------------------------
// helpers
// ---------------------------------------------------------------------------
__device__ __forceinline__ void mma_f16(float* d, const unsigned* a, const unsigned* b) {
    asm volatile(
        "mma.sync.aligned.m16n8k16.row.col.f32.f16.f16.f32 "
        "{%0,%1,%2,%3}, {%4,%5,%6,%7}, {%8,%9}, {%0,%1,%2,%3};\n"
        : "+f"(d[0]), "+f"(d[1]), "+f"(d[2]), "+f"(d[3])
        : "r"(a[0]), "r"(a[1]), "r"(a[2]), "r"(a[3]),
          "r"(b[0]), "r"(b[1]));
}

__device__ __forceinline__ void ldsm_x4(unsigned& r0, unsigned& r1,
                                        unsigned& r2, unsigned& r3, unsigned a) {
    asm volatile("ldmatrix.sync.aligned.m8n8.x4.shared.b16 {%0,%1,%2,%3}, [%4];"
                 : "=r"(r0), "=r"(r1), "=r"(r2), "=r"(r3) : "r"(a));
}
#define STSM_X2(addr, r0, r1) \
    asm volatile("stmatrix.sync.aligned.m8n8.x2.shared.b16 [%0], {%1,%2};" \
                 :: "r"(addr), "r"(r0), "r"(r1))

__device__ __forceinline__ unsigned h2u(float a, float b) {
    __half2 h = __floats2half2_rn(a, b);
    return reinterpret_cast<unsigned&>(h);
}

__device__ __forceinline__ unsigned smaddr(const void* p) {
    return (unsigned)__cvta_generic_to_shared(p);
}
#define CPA16(dst, src) asm volatile("cp.async.cg.shared.global [%0], [%1], 16;" :: "r"(dst), "l"(src))
#define CPCOMMIT()      asm volatile("cp.async.commit_group;")
#define CPWAIT1()       asm volatile("cp.async.wait_group 1;")

__device__ __forceinline__ float gelu_exact(float v) {
    return 0.5f * v * (1.0f + erff(v * 0.70710678118654752f));
}

// ---------------------------------------------------------------------------
// Batched prep: all 8 weight transposes (fp32 [K][N] -> f16 [N][K]) in ONE
// kernel. Tile grid per layer: qkv 6x18=108, proj 6x6=36, w1 6x24=144,
// w2 24x6=144 -> 432/layer, 864 total.
// ---------------------------------------------------------------------------
__global__ void transpose_all_kernel(const float* __restrict__ qkv_w,
                                     const float* __restrict__ proj_w,
                                     const float* __restrict__ w1,
                                     const float* __restrict__ w2) {
    __shared__ float t[32][33];
    int idx = blockIdx.x;
    const int layer = idx / 432;
    int r = idx % 432;

    const float* src;
    __half* dst;
    int K, N, kt, nt;
    if (r < 108) {                     // qkv: K=192, N=576 (6 x 18 tiles)
        K = CDIM; N = QKVN;
        kt = r / 18; nt = r % 18;
        src = qkv_w + (size_t)layer * CDIM * QKVN;
        dst = g_wt16 + WQ_OFF + (size_t)layer * CDIM * QKVN;
    } else if (r < 144) {              // proj: 192x192 (6 x 6)
        r -= 108; K = CDIM; N = CDIM;
        kt = r / 6; nt = r % 6;
        src = proj_w + (size_t)layer * CDIM * CDIM;
        dst = g_wt16 + WP_OFF + (size_t)layer * CDIM * CDIM;
    } else if (r < 288) {              // w1: K=192, N=768 (6 x 24)
        r -= 144; K = CDIM; N = FFN;
        kt = r / 24; nt = r % 24;
        src = w1 + (size_t)layer * CDIM * FFN;
        dst = g_wt16 + W1_OFF + (size_t)layer * CDIM * FFN;
    } else {                           // w2: K=768, N=192 (24 x 6)
        r -= 288; K = FFN; N = CDIM;
        kt = r / 6; nt = r % 6;
        src = w2 + (size_t)layer * FFN * CDIM;
        dst = g_wt16 + W2_OFF + (size_t)layer * FFN * CDIM;
    }

    const int n0 = nt * 32, k0 = kt * 32;
    const int tx = threadIdx.x, ty = threadIdx.y;   // 32 x 8
    #pragma unroll
    for (int i = 0; i < 32; i += 8)
        t[ty + i][tx] = src[(size_t)(k0 + ty + i) * N + n0 + tx];
    __syncthreads();
    #pragma unroll
    for (int i = 0; i < 32; i += 8)
        dst[(size_t)(n0 + ty + i) * K + k0 + tx] = __float2half_rn(t[tx][ty + i]);
}

__global__ void cvt_f16_kernel(const float* __restrict__ src,
                               __half* __restrict__ dst, int n) {
    int i = blockIdx.x * blockDim.x + threadIdx.x;
    if (i < n) dst[i] = __float2half_rn(src[i]);
}

// ---------------------------------------------------------------------------
// Dense (relative-position bias + shift mask)
// ---------------------------------------------------------------------------
__global__ void biasmask_kernel(const float* __restrict__ table) {
    size_t idx = (size_t)blockIdx.x * blockDim.x + threadIdx.x;
    size_t total = (size_t)2 * TWIN * NHEAD * NTOK * NTOK;
    if (idx >= total) return;
    int m = idx % NTOK; size_t r = idx / NTOK;
    int n = r % NTOK;   r /= NTOK;
    int head = r % NHEAD; r /= NHEAD;
    int t = r % TWIN;   int L = (int)(r / TWIN);
    int z1 = n / 72, h1 = (n % 72) / 12, w1 = n % 12;
    int z2 = m / 72, h2 = (m % 72) / 12, w2 = m % 12;
    int pos = 828 * (z1 + 2 * z2) + 23 * (h1 + 6 * h2) + (w1 - w2 + 11);
    float v = table[(((size_t)L * NB + pos) * TWIN + t) * NHEAD + head];
    if (L == 1) {
        int tz = t / 8, th = t % 8;
        int idn = (((tz * 2 + z1) >= 1) ? 2 : 0) + (((th * 6 + h1) >= 3) ? 1 : 0);
        int idm = (((tz * 2 + z2) >= 1) ? 2 : 0) + (((th * 6 + h2) >= 3) ? 1 : 0);
        if (idn != idm) v += -10000.0f;
    }
    g_bm[idx] = v;
}

// ---------------------------------------------------------------------------
// f16 GEMM (m16n8k16, fp32 accum), ldmatrix fragments, 3-stage cp.async
// pipeline with ONE __syncthreads per iteration (refill stage (it+2)%3
// after the barrier: the barrier orders all iter-1 LDSM reads of that slot).
// BM=128, BN=64, BK=32, 256 thr / 8 warps (4m x 2n), warp tile 32x32.
// ---------------------------------------------------------------------------
#define ASTG16 (128 * 40)
#define BSTG16 (64 * 40)
#define GEMM_SMEM16 ((3 * ASTG16 + 3 * BSTG16) * 2)   // 46080 B

template <int EPI, int GATHER, int OUTH>
__global__ void __launch_bounds__(256, 3)
hgemm_kernel(const __half* __restrict__ A,
             const __half* __restrict__ B,
             const float* __restrict__ bias,
             void* __restrict__ Cout,
             int K, int Nn, int rolled) {
    extern __shared__ __half hsm[];
    __half* As = hsm;
    __half* Bs = hsm + 3 * ASTG16;

    const int tid  = threadIdx.x;
    const int lane = tid & 31;
    const int wid  = tid >> 5;
    const int wm   = wid >> 1;          // 0..3
    const int wn   = wid & 1;           // 0..1
    const int g    = lane >> 2;
    const int tg   = lane & 3;
    const int m0   = blockIdx.y * 128;
    const int n0   = blockIdx.x * 64;

    // ldmatrix per-lane byte offsets (proven mapping from R10)
    const unsigned lrow = lane & 7;
    const unsigned lsel = (lane >> 3) & 1;
    const unsigned lhi  = lane >> 4;
    const unsigned aoff = ((lrow + lsel * 8) * 40 + lhi * 8) * 2;
    const unsigned boff = ((lrow + lhi * 8) * 40 + lsel * 8) * 2;

    // copy roles
    const int arow = tid >> 1;
    const int ac0  = (tid & 1) * 2;
    const int brow = tid >> 2;
    const int bchk = tid & 3;

    size_t arowp;
    {
        int r = m0 + arow;
        if (GATHER) {
            int n = r % NTOK, win = r / NTOK;
            int l = win % NWW, t = win / NWW;
            int tz = t / 8, th = t % 8;
            int z1 = n / 72, h1 = (n % 72) / 12, w1 = n % 12;
            int zr = tz * 2 + z1, hr = th * 6 + h1, wr = l * 12 + w1;
            int z, hh, ww;
            if (rolled) { z = (zr + 7) & 7; hh = (hr + 45) % 48; ww = (wr + 186) % 192; }
            else        { z = zr; hh = hr; ww = wr; }
            arowp = ((size_t)z * 48 + hh) * 192 + ww;
        } else {
            arowp = (size_t)r;
        }
    }
    const __half* aSrc = A + arowp * K;
    const __half* bSrc = B + (size_t)(n0 + brow) * K;

    float acc[2][4][4];
    #pragma unroll
    for (int mt = 0; mt < 2; mt++)
        #pragma unroll
        for (int nt = 0; nt < 4; nt++)
            #pragma unroll
            for (int i = 0; i < 4; i++) acc[mt][nt][i] = 0.0f;

    // prologue: stages 0,1
    #pragma unroll
    for (int s = 0; s < 2; s++) {
        __half* as = As + s * ASTG16;
        __half* bs = Bs + s * BSTG16;
        const int k0 = s * 32;
        #pragma unroll
        for (int j = 0; j < 2; j++)
            CPA16(smaddr(as + arow * 40 + (ac0 + j) * 8), aSrc + k0 + (ac0 + j) * 8);
        CPA16(smaddr(bs + brow * 40 + bchk * 8), bSrc + k0 + bchk * 8);
        CPCOMMIT();
    }

    const int iters = K >> 5;
    int cur = 0;
    for (int it = 0; it < iters; it++) {
        CPWAIT1();
        __syncthreads();

        // refill the stage consumed two iterations ago
        const int k0n = (it + 2) << 5;
        if (k0n < K) {
            const int stg = (cur + 2) % 3;
            __half* asw = As + stg * ASTG16;
            __half* bsw = Bs + stg * BSTG16;
            #pragma unroll
            for (int j = 0; j < 2; j++)
                CPA16(smaddr(asw + arow * 40 + (ac0 + j) * 8), aSrc + k0n + (ac0 + j) * 8);
            CPA16(smaddr(bsw + brow * 40 + bchk * 8), bSrc + k0n + bchk * 8);
        }
        CPCOMMIT();

        const __half* as = As + cur * ASTG16;
        const __half* bs = Bs + cur * BSTG16;
        const unsigned aB = smaddr(as) + (unsigned)(wm * 32 * 40) * 2 + aoff;
        const unsigned bB = smaddr(bs) + (unsigned)(wn * 32 * 40) * 2 + boff;
        #pragma unroll
        for (int kk2 = 0; kk2 < 2; kk2++) {
            unsigned af[2][4], bf[4][2];
            ldsm_x4(af[0][0], af[0][1], af[0][2], af[0][3], aB + kk2 * 32);
            ldsm_x4(af[1][0], af[1][1], af[1][2], af[1][3], aB + 1280 + kk2 * 32);
            ldsm_x4(bf[0][0], bf[0][1], bf[1][0], bf[1][1], bB + kk2 * 32);
            ldsm_x4(bf[2][0], bf[2][1], bf[3][0], bf[3][1], bB + 1280 + kk2 * 32);
            #pragma unroll
            for (int mt = 0; mt < 2; mt++)
                #pragma unroll
                for (int nt = 0; nt < 4; nt++)
                    mma_f16(acc[mt][nt], af[mt], bf[nt]);
        }
        cur = (cur + 1) % 3;
    }

    #pragma unroll
    for (int mt = 0; mt < 2; mt++) {
        int r0 = m0 + wm * 32 + mt * 16 + g;
        #pragma unroll
        for (int nt = 0; nt < 4; nt++) {
            int c = n0 + wn * 32 + nt * 8 + tg * 2;
            float b0 = bias[c], b1 = bias[c + 1];
            float v0 = acc[mt][nt][0] + b0;
            float v1 = acc[mt][nt][1] + b1;
            float v2 = acc[mt][nt][2] + b0;
            float v3 = acc[mt][nt][3] + b1;
            if (EPI == 1) {
                v0 = gelu_exact(v0); v1 = gelu_exact(v1);
                v2 = gelu_exact(v2); v3 = gelu_exact(v3);
            }
            if (OUTH) {
                __half* C16 = (__half*)Cout;
                *reinterpret_cast<__half2*>(C16 + (size_t)r0 * Nn + c) =
                    __floats2half2_rn(v0, v1);
                *reinterpret_cast<__half2*>(C16 + (size_t)(r0 + 8) * Nn + c) =
                    __floats2half2_rn(v2, v3);
            } else {
                float* Cf = (float*)Cout;
                *reinterpret_cast<float2*>(Cf + (size_t)r0 * Nn + c)       = make_float2(v0, v1);
                *reinterpret_cast<float2*>(Cf + (size_t)(r0 + 8) * Nn + c) = make_float2(v2, v3);
            }
        }
    }
}

// ---------------------------------------------------------------------------
// f16 tensor-core window attention (unchanged from R10 — proven bit-exact).
// ---------------------------------------------------------------------------
#define KS16_S 40
#define VT16_S 152
#define SCR16_S 152
#define ATTN_SMEM16 ((NTOK * KS16_S + HD * VT16_S + 4 * 16 * SCR16_S) * 2)  // 40704 B

__global__ void __launch_bounds__(128, 3) attn_f16_kernel(int L) {
    const int win  = blockIdx.x;
    const int head = blockIdx.y;
    const int t    = win >> 4;
    extern __shared__ __half smh[];
    __half* ks  = smh;                        // [144][40]
    __half* vsT = ks + NTOK * KS16_S;         // [32][152]  (V transposed)
    __half* scr = vsT + HD * VT16_S;          // 4 x [16][152]

    const int tid  = threadIdx.x;
    const int lane = tid & 31;
    const int wid  = tid >> 5;
    const int g    = lane >> 2;
    const int tg   = lane & 3;

    const unsigned lrow = lane & 7;
    const unsigned lsel = (lane >> 3) & 1;
    const unsigned lhi  = lane >> 4;
    const unsigned kboff = ((lrow + lhi * 8) * KS16_S + lsel * 8) * 2;   // B-style
    const unsigned paoff = ((lrow + lsel * 8) * SCR16_S + lhi * 8) * 2;  // A-style
    const unsigned vboff = ((lrow + lhi * 8) * VT16_S + lsel * 8) * 2;   // B-style

    const __half* base = g_qkv16 + (size_t)win * NTOK * QKVN;
    const int hc = head * HD;
    for (int idx = tid; idx < NTOK * 4; idx += 128) {
        int row = idx >> 2, c = idx & 3;
        *reinterpret_cast<uint4*>(&ks[row * KS16_S + c * 8]) =
            *reinterpret_cast<const uint4*>(base + (size_t)row * QKVN + CDIM + hc + c * 8);
        uint4 v4 = *reinterpret_cast<const uint4*>(base + (size_t)row * QKVN + 2 * CDIM + hc + c * 8);
        const __half* hv = reinterpret_cast<const __half*>(&v4);
        #pragma unroll
        for (int j = 0; j < 8; j++)
            vsT[(c * 8 + j) * VT16_S + row] = hv[j];
    }
    __syncthreads();

    const float* bmb = g_bm + (((size_t)L * TWIN + t) * NHEAD + head) * NTOK * NTOK;
    __half* wscr = scr + wid * 16 * SCR16_S;
    const unsigned kbase  = smaddr(ks) + kboff;
    const unsigned pbase  = smaddr(wscr) + paoff;
    const unsigned vbase  = smaddr(vsT) + vboff;
    const unsigned stbase = smaddr(wscr) + (unsigned)((lane & 15) * SCR16_S) * 2;
    const float sc = 0.17677669529663687f;   // 1/sqrt(32)

    for (int mt = wid; mt < 9; mt += 4) {
        const int rb = mt * 16;

        const __half* qA = g_qkv16 + (size_t)(win * NTOK + rb + g) * QKVN + hc;
        const __half* qB = g_qkv16 + (size_t)(win * NTOK + rb + 8 + g) * QKVN + hc;
        unsigned aq[2][4];
        #pragma unroll
        for (int kk2 = 0; kk2 < 2; kk2++) {
            const int kk = kk2 * 16 + 2 * tg;
            aq[kk2][0] = *reinterpret_cast<const unsigned*>(qA + kk);
            aq[kk2][1] = *reinterpret_cast<const unsigned*>(qB + kk);
            aq[kk2][2] = *reinterpret_cast<const unsigned*>(qA + kk + 8);
            aq[kk2][3] = *reinterpret_cast<const unsigned*>(qB + kk + 8);
        }

        float sacc[18][4];
        #pragma unroll
        for (int ntp = 0; ntp < 9; ntp++) {
            float* s0 = sacc[2 * ntp];
            float* s1 = sacc[2 * ntp + 1];
            #pragma unroll
            for (int i = 0; i < 4; i++) { s0[i] = 0.0f; s1[i] = 0.0f; }
            #pragma unroll
            for (int kk2 = 0; kk2 < 2; kk2++) {
                unsigned b0, b1, b2, b3;
                ldsm_x4(b0, b1, b2, b3, kbase + ntp * (16 * KS16_S * 2) + kk2 * 32);
                unsigned bfa[2] = {b0, b1}, bfb[2] = {b2, b3};
                mma_f16(s0, aq[kk2], bfa);
                mma_f16(s1, aq[kk2], bfb);
            }
            #pragma unroll
            for (int h = 0; h < 2; h++) {
                float* sv = h ? s1 : s0;
                const int cb = (2 * ntp + h) * 8;
                const float2 bA = *reinterpret_cast<const float2*>(
                    bmb + (size_t)(rb + g) * NTOK + cb + tg * 2);
                const float2 bB = *reinterpret_cast<const float2*>(
                    bmb + (size_t)(rb + 8 + g) * NTOK + cb + tg * 2);
                sv[0] = fmaf(sv[0], sc, bA.x);
                sv[1] = fmaf(sv[1], sc, bA.y);
                sv[2] = fmaf(sv[2], sc, bB.x);
                sv[3] = fmaf(sv[3], sc, bB.y);
            }
        }

        float mxA = -1e30f, mxB = -1e30f;
        #pragma unroll
        for (int nt = 0; nt < 18; nt++) {
            mxA = fmaxf(mxA, fmaxf(sacc[nt][0], sacc[nt][1]));
            mxB = fmaxf(mxB, fmaxf(sacc[nt][2], sacc[nt][3]));
        }
        #pragma unroll
        for (int o = 1; o <= 2; o <<= 1) {
            mxA = fmaxf(mxA, __shfl_xor_sync(0xFFFFFFFFu, mxA, o));
            mxB = fmaxf(mxB, __shfl_xor_sync(0xFFFFFFFFu, mxB, o));
        }
        float smA = 0.0f, smB = 0.0f;
        #pragma unroll
        for (int nt = 0; nt < 18; nt++) {
            sacc[nt][0] = __expf(sacc[nt][0] - mxA);
            sacc[nt][1] = __expf(sacc[nt][1] - mxA);
            sacc[nt][2] = __expf(sacc[nt][2] - mxB);
            sacc[nt][3] = __expf(sacc[nt][3] - mxB);
            smA += sacc[nt][0] + sacc[nt][1];
            smB += sacc[nt][2] + sacc[nt][3];
        }
        #pragma unroll
        for (int o = 1; o <= 2; o <<= 1) {
            smA += __shfl_xor_sync(0xFFFFFFFFu, smA, o);
            smB += __shfl_xor_sync(0xFFFFFFFFu, smB, o);
        }
        const float invA = 1.0f / smA;
        const float invB = 1.0f / smB;

        #pragma unroll
        for (int nt = 0; nt < 18; nt++) {
            unsigned r0 = h2u(sacc[nt][0], sacc[nt][1]);
            unsigned r1 = h2u(sacc[nt][2], sacc[nt][3]);
            STSM_X2(stbase + nt * 16, r0, r1);
        }
        __syncwarp();

        float oacc[4][4];
        #pragma unroll
        for (int nt = 0; nt < 4; nt++)
            oacc[nt][0] = oacc[nt][1] = oacc[nt][2] = oacc[nt][3] = 0.0f;
        #pragma unroll
        for (int kk = 0; kk < 9; kk++) {
            unsigned ap[4];
            ldsm_x4(ap[0], ap[1], ap[2], ap[3], pbase + kk * 32);
            unsigned b0, b1, b2, b3, c0, c1, c2, c3;
            ldsm_x4(b0, b1, b2, b3, vbase + kk * 32);
            ldsm_x4(c0, c1, c2, c3, vbase + (16 * VT16_S * 2) + kk * 32);
            { unsigned bf[2] = {b0, b1}; mma_f16(oacc[0], ap, bf); }
            { unsigned bf[2] = {b2, b3}; mma_f16(oacc[1], ap, bf); }
            { unsigned bf[2] = {c0, c1}; mma_f16(oacc[2], ap, bf); }
            { unsigned bf[2] = {c2, c3}; mma_f16(oacc[3], ap, bf); }
        }
        __syncwarp();

        #pragma unroll
        for (int nt = 0; nt < 4; nt++) {
            const int c = nt * 8 + tg * 2;
            __half* opA = g_ao16 + ((size_t)win * NTOK + rb + g) * CDIM + hc + c;
            __half* opB = g_ao16 + ((size_t)win * NTOK + rb + 8 + g) * CDIM + hc + c;
            *reinterpret_cast<__half2*>(opA) =
                __floats2half2_rn(oacc[nt][0] * invA, oacc[nt][1] * invA);
            *reinterpret_cast<__half2*>(opB) =
                __floats2half2_rn(oacc[nt][2] * invB, oacc[nt][3] * invB);
        }
    }
}

// ---------------------------------------------------------------------------
// LayerNorm + residual: xout[p] = xin[p] + LN(y[r])*g + b; optional f16 copy.
// ---------------------------------------------------------------------------
__global__ void ln_add_kernel(const float* __restrict__ y,
                              const float* __restrict__ g,
                              const float* __restrict__ b,
                              const float* __restrict__ xin,
                              float* __restrict__ xout,
                              __half* __restrict__ xh16,
                              int mode) {
    int w = (blockIdx.x * blockDim.x + threadIdx.x) >> 5;
    int lane = threadIdx.x & 31;
    if (w >= MTOK) return;
    size_t p;
    if (mode == 0) {
        p = (size_t)w;
    } else {
        int n = w % NTOK, win = w / NTOK;
        int l = win % NWW, t = win / NWW;
        int tz = t / 8, th = t % 8;
        int z1 = n / 72, h1 = (n % 72) / 12, w1 = n % 12;
        int zr = tz * 2 + z1, hr = th * 6 + h1, wr = l * 12 + w1;
        int z, hh, ww;
        if (mode == 2) { z = (zr + 7) & 7; hh = (hr + 45) % 48; ww = (wr + 186) % 192; }
        else           { z = zr; hh = hr; ww = wr; }
        p = ((size_t)z * 48 + hh) * 192 + ww;
    }
    const float* yr = y + (size_t)w * CDIM;
    float v[6];
    float sum = 0.0f;
    #pragma unroll
    for (int i = 0; i < 6; i++) { v[i] = yr[lane + 32 * i]; sum += v[i]; }
    #pragma unroll
    for (int o = 16; o; o >>= 1) sum += __shfl_xor_sync(0xFFFFFFFFu, sum, o);
    float mu = sum * (1.0f / 192.0f);
    float var = 0.0f;
    #pragma unroll
    for (int i = 0; i < 6; i++) { float d = v[i] - mu; var += d * d; }
    #pragma unroll
    for (int o = 16; o; o >>= 1) var += __shfl_xor_sync(0xFFFFFFFFu, var, o);
    var *= (1.0f / 192.0f);
    float rs = rsqrtf(var + 1e-5f);
    const float* xi = xin + p * CDIM;
    float* xo = xout + p * CDIM;
    #pragma unroll
    for (int i = 0; i < 6; i++) {
        int c = lane + 32 * i;
        float val = xi[c] + (v[i] - mu) * rs * g[c] + b[c];
        xo[c] = val;
        if (xh16) xh16[p * CDIM + c] = __float2half_rn(val);
    }
}

extern "C" void kernel_launch(void* const* d_in, const int* in_sizes, int n_in,
                              void* d_out, int out_size) {
    const float* x_in       = (const float*)d_in[0];
    const float* qkv_w      = (const float*)d_in[1];
    const float* qkv_b      = (const float*)d_in[2];
    const float* proj_w     = (const float*)d_in[3];
    const float* proj_b     = (const float*)d_in[4];
    const float* bias_table = (const float*)d_in[5];
    const float* n1_g       = (const float*)d_in[6];
    const float* n1_b       = (const float*)d_in[7];
    const float* n2_g       = (const float*)d_in[8];
    const float* n2_b       = (const float*)d_in[9];
    const float* w1         = (const float*)d_in[10];
    const float* b1         = (const float*)d_in[11];
    const float* w2         = (const float*)d_in[12];
    const float* b2         = (const float*)d_in[13];
    // d_in[14..16] = Z,H,W scalars (fixed 8,48,192)

    float  *gx, *gtmp;
    __half *gxh, *gqkv, *gao, *gh, *gwt;
    cudaGetSymbolAddress((void**)&gx,   g_x);
    cudaGetSymbolAddress((void**)&gtmp, g_tmp);
    cudaGetSymbolAddress((void**)&gxh,  g_xh16);
    cudaGetSymbolAddress((void**)&gqkv, g_qkv16);
    cudaGetSymbolAddress((void**)&gao,  g_ao16);
    cudaGetSymbolAddress((void**)&gh,   g_h16);
    cudaGetSymbolAddress((void**)&gwt,  g_wt16);

    cudaFuncSetAttribute(hgemm_kernel<0,1,1>, cudaFuncAttributeMaxDynamicSharedMemorySize, GEMM_SMEM16);
    cudaFuncSetAttribute(hgemm_kernel<0,0,0>, cudaFuncAttributeMaxDynamicSharedMemorySize, GEMM_SMEM16);
    cudaFuncSetAttribute(hgemm_kernel<1,0,1>, cudaFuncAttributeMaxDynamicSharedMemorySize, GEMM_SMEM16);
    cudaFuncSetAttribute(attn_f16_kernel, cudaFuncAttributeMaxDynamicSharedMemorySize, ATTN_SMEM16);

    // prep: ONE batched transpose launch; cvt x_in; bias table
    transpose_all_kernel<<<864, dim3(32, 8)>>>(qkv_w, proj_w, w1, w2);
    cvt_f16_kernel<<<(MTOK * CDIM + 255) / 256, 256>>>(x_in, gxh, MTOK * CDIM);
    {
        size_t total = (size_t)2 * TWIN * NHEAD * NTOK * NTOK;
        biasmask_kernel<<<(unsigned)((total + 255) / 256), 256>>>(bias_table);
    }

    for (int L = 0; L < 2; L++) {
        const float* xsrc = (L == 0) ? x_in : gx;

        // QKV (fused window gather), f16 out
        hgemm_kernel<0,1,1><<<dim3(QKVN / 64, MTOK / 128), 256, GEMM_SMEM16>>>(
            gxh, gwt + WQ_OFF + (size_t)L * CDIM * QKVN, qkv_b + (size_t)L * QKVN,
            gqkv, CDIM, QKVN, L);

        attn_f16_kernel<<<dim3(NWIN, NHEAD), 128, ATTN_SMEM16>>>(L);

        // proj: f16 in, fp32 out
        hgemm_kernel<0,0,0><<<dim3(CDIM / 64, MTOK / 128), 256, GEMM_SMEM16>>>(
            gao, gwt + WP_OFF + (size_t)L * CDIM * CDIM, proj_b + (size_t)L * CDIM,
            gtmp, CDIM, CDIM, 0);

        // x = xsrc + LN(un-window(proj_out));  + f16 copy for next GEMM
        ln_add_kernel<<<(MTOK * 32 + 255) / 256, 256>>>(
            gtmp, n1_g + (size_t)L * CDIM, n1_b + (size_t)L * CDIM,
            xsrc, gx, gxh, L ? 2 : 1);

        // MLP up: gelu, f16 out
        hgemm_kernel<1,0,1><<<dim3(FFN / 64, MTOK / 128), 256, GEMM_SMEM16>>>(
            gxh, gwt + W1_OFF + (size_t)L * CDIM * FFN, b1 + (size_t)L * FFN,
            gh, CDIM, FFN, 0);

        // MLP down: f16 in, fp32 out
        hgemm_kernel<0,0,0><<<dim3(CDIM / 64, MTOK / 128), 256, GEMM_SMEM16>>>(
            gh, gwt + W2_OFF + (size_t)L * FFN * CDIM, b2 + (size_t)L * CDIM,
            gtmp, FFN, CDIM, 0);

        // x = x + LN(mlp_out); final layer writes straight to d_out
        float*  xo  = (L == 1) ? (float*)d_out : gx;
        __half* xho = (L == 1) ? (__half*)nullptr : gxh;
        ln_add_kernel<<<(MTOK * 32 + 255) / 256, 256>>>(
            gtmp, n2_g + (size_t)L * CDIM, n2_b + (size_t)L * CDIM,
            gx, xo, xho, 0);
    }
}

// round 14
// speedup vs baseline: 1.9060x; 1.0032x over previous
#include <cuda_runtime.h>
#include <cuda_fp16.h>
#include <math.h>

#define MTOK   73728
#define CDIM   192
#define NHEAD  6
#define HD     32
#define NTOK   144
#define NWIN   512
#define TWIN   32
#define NWW    16
#define NB     3312
#define QKVN   576
#define FFN    768

// fp32 buffers (residual stream, bias table)
__device__ float  g_x   [(size_t)MTOK * CDIM];
__device__ float  g_bm  [(size_t)2 * TWIN * NHEAD * NTOK * NTOK];
// f16 activation buffers
__device__ __half g_xh16 [(size_t)MTOK * CDIM];
__device__ __half g_qkv16[(size_t)MTOK * QKVN];   // QKV out; also MLP-down out
__device__ __half g_ao16 [(size_t)MTOK * CDIM];
__device__ __half g_h16  [(size_t)MTOK * FFN];    // MLP hidden; also proj out
// f16 transposed weights [N][K]: qkv | proj | w1 | w2 (both layers)
#define WQ_OFF 0
#define WP_OFF 221184
#define W1_OFF 294912
#define W2_OFF 589824
__device__ __half g_wt16[884736];

// ---------------------------------------------------------------------------
// helpers
// ---------------------------------------------------------------------------
__device__ __forceinline__ void mma_f16(float* d, const unsigned* a, const unsigned* b) {
    asm volatile(
        "mma.sync.aligned.m16n8k16.row.col.f32.f16.f16.f32 "
        "{%0,%1,%2,%3}, {%4,%5,%6,%7}, {%8,%9}, {%0,%1,%2,%3};\n"
        : "+f"(d[0]), "+f"(d[1]), "+f"(d[2]), "+f"(d[3])
        : "r"(a[0]), "r"(a[1]), "r"(a[2]), "r"(a[3]),
          "r"(b[0]), "r"(b[1]));
}

__device__ __forceinline__ void ldsm_x4(unsigned& r0, unsigned& r1,
                                        unsigned& r2, unsigned& r3, unsigned a) {
    asm volatile("ldmatrix.sync.aligned.m8n8.x4.shared.b16 {%0,%1,%2,%3}, [%4];"
                 : "=r"(r0), "=r"(r1), "=r"(r2), "=r"(r3) : "r"(a));
}
#define STSM_X2(addr, r0, r1) \
    asm volatile("stmatrix.sync.aligned.m8n8.x2.shared.b16 [%0], {%1,%2};" \
                 :: "r"(addr), "r"(r0), "r"(r1))

__device__ __forceinline__ unsigned h2u(float a, float b) {
    __half2 h = __floats2half2_rn(a, b);
    return reinterpret_cast<unsigned&>(h);
}

__device__ __forceinline__ unsigned smaddr(const void* p) {
    return (unsigned)__cvta_generic_to_shared(p);
}
#define CPA16(dst, src) asm volatile("cp.async.cg.shared.global [%0], [%1], 16;" :: "r"(dst), "l"(src))
#define CPCOMMIT()      asm volatile("cp.async.commit_group;")
#define CPWAIT1()       asm volatile("cp.async.wait_group 1;")

__device__ __forceinline__ float gelu_exact(float v) {
    return 0.5f * v * (1.0f + erff(v * 0.70710678118654752f));
}

// ---------------------------------------------------------------------------
// Batched prep: all 8 weight transposes (fp32 [K][N] -> f16 [N][K]); 864 tiles.
// ---------------------------------------------------------------------------
__global__ void transpose_all_kernel(const float* __restrict__ qkv_w,
                                     const float* __restrict__ proj_w,
                                     const float* __restrict__ w1,
                                     const float* __restrict__ w2) {
    __shared__ float t[32][33];
    int idx = blockIdx.x;
    const int layer = idx / 432;
    int r = idx % 432;

    const float* src;
    __half* dst;
    int K, N, kt, nt;
    if (r < 108) {
        K = CDIM; N = QKVN;
        kt = r / 18; nt = r % 18;
        src = qkv_w + (size_t)layer * CDIM * QKVN;
        dst = g_wt16 + WQ_OFF + (size_t)layer * CDIM * QKVN;
    } else if (r < 144) {
        r -= 108; K = CDIM; N = CDIM;
        kt = r / 6; nt = r % 6;
        src = proj_w + (size_t)layer * CDIM * CDIM;
        dst = g_wt16 + WP_OFF + (size_t)layer * CDIM * CDIM;
    } else if (r < 288) {
        r -= 144; K = CDIM; N = FFN;
        kt = r / 24; nt = r % 24;
        src = w1 + (size_t)layer * CDIM * FFN;
        dst = g_wt16 + W1_OFF + (size_t)layer * CDIM * FFN;
    } else {
        r -= 288; K = FFN; N = CDIM;
        kt = r / 6; nt = r % 6;
        src = w2 + (size_t)layer * FFN * CDIM;
        dst = g_wt16 + W2_OFF + (size_t)layer * FFN * CDIM;
    }

    const int n0 = nt * 32, k0 = kt * 32;
    const int tx = threadIdx.x, ty = threadIdx.y;
    #pragma unroll
    for (int i = 0; i < 32; i += 8)
        t[ty + i][tx] = src[(size_t)(k0 + ty + i) * N + n0 + tx];
    __syncthreads();
    #pragma unroll
    for (int i = 0; i < 32; i += 8)
        dst[(size_t)(n0 + ty + i) * K + k0 + tx] = __float2half_rn(t[tx][ty + i]);
}

__global__ void cvt_f16_kernel(const float* __restrict__ src,
                               __half* __restrict__ dst, int n) {
    int i = blockIdx.x * blockDim.x + threadIdx.x;
    if (i < n) dst[i] = __float2half_rn(src[i]);
}

// ---------------------------------------------------------------------------
// Dense (relative-position bias + shift mask)
// ---------------------------------------------------------------------------
__global__ void biasmask_kernel(const float* __restrict__ table) {
    size_t idx = (size_t)blockIdx.x * blockDim.x + threadIdx.x;
    size_t total = (size_t)2 * TWIN * NHEAD * NTOK * NTOK;
    if (idx >= total) return;
    int m = idx % NTOK; size_t r = idx / NTOK;
    int n = r % NTOK;   r /= NTOK;
    int head = r % NHEAD; r /= NHEAD;
    int t = r % TWIN;   int L = (int)(r / TWIN);
    int z1 = n / 72, h1 = (n % 72) / 12, w1 = n % 12;
    int z2 = m / 72, h2 = (m % 72) / 12, w2 = m % 12;
    int pos = 828 * (z1 + 2 * z2) + 23 * (h1 + 6 * h2) + (w1 - w2 + 11);
    float v = table[(((size_t)L * NB + pos) * TWIN + t) * NHEAD + head];
    if (L == 1) {
        int tz = t / 8, th = t % 8;
        int idn = (((tz * 2 + z1) >= 1) ? 2 : 0) + (((th * 6 + h1) >= 3) ? 1 : 0);
        int idm = (((tz * 2 + z2) >= 1) ? 2 : 0) + (((th * 6 + h2) >= 3) ? 1 : 0);
        if (idn != idm) v += -10000.0f;
    }
    g_bm[idx] = v;
}

// ---------------------------------------------------------------------------
// f16 GEMM (m16n8k16, fp32 accum), ldmatrix fragments, 3-stage cp.async
// pipeline, ONE __syncthreads per iteration.  (Proven R11 kernel.)
// BM=128, BN=64, BK=32, 256 thr / 8 warps (4m x 2n), warp tile 32x32.
// ---------------------------------------------------------------------------
#define ASTG16 (128 * 40)
#define BSTG16 (64 * 40)
#define GEMM_SMEM16 ((3 * ASTG16 + 3 * BSTG16) * 2)   // 46080 B

template <int EPI, int GATHER, int OUTH>
__global__ void __launch_bounds__(256, 3)
hgemm_kernel(const __half* __restrict__ A,
             const __half* __restrict__ B,
             const float* __restrict__ bias,
             void* __restrict__ Cout,
             int K, int Nn, int rolled) {
    extern __shared__ __half hsm[];
    __half* As = hsm;
    __half* Bs = hsm + 3 * ASTG16;

    const int tid  = threadIdx.x;
    const int lane = tid & 31;
    const int wid  = tid >> 5;
    const int wm   = wid >> 1;
    const int wn   = wid & 1;
    const int g    = lane >> 2;
    const int tg   = lane & 3;
    const int m0   = blockIdx.y * 128;
    const int n0   = blockIdx.x * 64;

    const unsigned lrow = lane & 7;
    const unsigned lsel = (lane >> 3) & 1;
    const unsigned lhi  = lane >> 4;
    const unsigned aoff = ((lrow + lsel * 8) * 40 + lhi * 8) * 2;
    const unsigned boff = ((lrow + lhi * 8) * 40 + lsel * 8) * 2;

    const int arow = tid >> 1;
    const int ac0  = (tid & 1) * 2;
    const int brow = tid >> 2;
    const int bchk = tid & 3;

    size_t arowp;
    {
        int r = m0 + arow;
        if (GATHER) {
            int n = r % NTOK, win = r / NTOK;
            int l = win % NWW, t = win / NWW;
            int tz = t / 8, th = t % 8;
            int z1 = n / 72, h1 = (n % 72) / 12, w1 = n % 12;
            int zr = tz * 2 + z1, hr = th * 6 + h1, wr = l * 12 + w1;
            int z, hh, ww;
            if (rolled) { z = (zr + 7) & 7; hh = (hr + 45) % 48; ww = (wr + 186) % 192; }
            else        { z = zr; hh = hr; ww = wr; }
            arowp = ((size_t)z * 48 + hh) * 192 + ww;
        } else {
            arowp = (size_t)r;
        }
    }
    const __half* aSrc = A + arowp * K;
    const __half* bSrc = B + (size_t)(n0 + brow) * K;

    float acc[2][4][4];
    #pragma unroll
    for (int mt = 0; mt < 2; mt++)
        #pragma unroll
        for (int nt = 0; nt < 4; nt++)
            #pragma unroll
            for (int i = 0; i < 4; i++) acc[mt][nt][i] = 0.0f;

    #pragma unroll
    for (int s = 0; s < 2; s++) {
        __half* as = As + s * ASTG16;
        __half* bs = Bs + s * BSTG16;
        const int k0 = s * 32;
        #pragma unroll
        for (int j = 0; j < 2; j++)
            CPA16(smaddr(as + arow * 40 + (ac0 + j) * 8), aSrc + k0 + (ac0 + j) * 8);
        CPA16(smaddr(bs + brow * 40 + bchk * 8), bSrc + k0 + bchk * 8);
        CPCOMMIT();
    }

    const int iters = K >> 5;
    int cur = 0;
    for (int it = 0; it < iters; it++) {
        CPWAIT1();
        __syncthreads();

        const int k0n = (it + 2) << 5;
        if (k0n < K) {
            const int stg = (cur + 2) % 3;
            __half* asw = As + stg * ASTG16;
            __half* bsw = Bs + stg * BSTG16;
            #pragma unroll
            for (int j = 0; j < 2; j++)
                CPA16(smaddr(asw + arow * 40 + (ac0 + j) * 8), aSrc + k0n + (ac0 + j) * 8);
            CPA16(smaddr(bsw + brow * 40 + bchk * 8), bSrc + k0n + bchk * 8);
        }
        CPCOMMIT();

        const __half* as = As + cur * ASTG16;
        const __half* bs = Bs + cur * BSTG16;
        const unsigned aB = smaddr(as) + (unsigned)(wm * 32 * 40) * 2 + aoff;
        const unsigned bB = smaddr(bs) + (unsigned)(wn * 32 * 40) * 2 + boff;
        #pragma unroll
        for (int kk2 = 0; kk2 < 2; kk2++) {
            unsigned af[2][4], bf[4][2];
            ldsm_x4(af[0][0], af[0][1], af[0][2], af[0][3], aB + kk2 * 32);
            ldsm_x4(af[1][0], af[1][1], af[1][2], af[1][3], aB + 1280 + kk2 * 32);
            ldsm_x4(bf[0][0], bf[0][1], bf[1][0], bf[1][1], bB + kk2 * 32);
            ldsm_x4(bf[2][0], bf[2][1], bf[3][0], bf[3][1], bB + 1280 + kk2 * 32);
            #pragma unroll
            for (int mt = 0; mt < 2; mt++)
                #pragma unroll
                for (int nt = 0; nt < 4; nt++)
                    mma_f16(acc[mt][nt], af[mt], bf[nt]);
        }
        cur = (cur + 1) % 3;
    }

    #pragma unroll
    for (int mt = 0; mt < 2; mt++) {
        int r0 = m0 + wm * 32 + mt * 16 + g;
        #pragma unroll
        for (int nt = 0; nt < 4; nt++) {
            int c = n0 + wn * 32 + nt * 8 + tg * 2;
            float b0 = bias[c], b1 = bias[c + 1];
            float v0 = acc[mt][nt][0] + b0;
            float v1 = acc[mt][nt][1] + b1;
            float v2 = acc[mt][nt][2] + b0;
            float v3 = acc[mt][nt][3] + b1;
            if (EPI == 1) {
                v0 = gelu_exact(v0); v1 = gelu_exact(v1);
                v2 = gelu_exact(v2); v3 = gelu_exact(v3);
            }
            if (OUTH) {
                __half* C16 = (__half*)Cout;
                *reinterpret_cast<__half2*>(C16 + (size_t)r0 * Nn + c) =
                    __floats2half2_rn(v0, v1);
                *reinterpret_cast<__half2*>(C16 + (size_t)(r0 + 8) * Nn + c) =
                    __floats2half2_rn(v2, v3);
            } else {
                float* Cf = (float*)Cout;
                *reinterpret_cast<float2*>(Cf + (size_t)r0 * Nn + c)       = make_float2(v0, v1);
                *reinterpret_cast<float2*>(Cf + (size_t)(r0 + 8) * Nn + c) = make_float2(v2, v3);
            }
        }
    }
}

// ---------------------------------------------------------------------------
// f16 tensor-core window attention (unchanged — proven bit-exact)
// ---------------------------------------------------------------------------
#define KS16_S 40
#define VT16_S 152
#define SCR16_S 152
#define ATTN_SMEM16 ((NTOK * KS16_S + HD * VT16_S + 4 * 16 * SCR16_S) * 2)

__global__ void __launch_bounds__(128, 3) attn_f16_kernel(int L) {
    const int win  = blockIdx.x;
    const int head = blockIdx.y;
    const int t    = win >> 4;
    extern __shared__ __half smh[];
    __half* ks  = smh;
    __half* vsT = ks + NTOK * KS16_S;
    __half* scr = vsT + HD * VT16_S;

    const int tid  = threadIdx.x;
    const int lane = tid & 31;
    const int wid  = tid >> 5;
    const int g    = lane >> 2;
    const int tg   = lane & 3;

    const unsigned lrow = lane & 7;
    const unsigned lsel = (lane >> 3) & 1;
    const unsigned lhi  = lane >> 4;
    const unsigned kboff = ((lrow + lhi * 8) * KS16_S + lsel * 8) * 2;
    const unsigned paoff = ((lrow + lsel * 8) * SCR16_S + lhi * 8) * 2;
    const unsigned vboff = ((lrow + lhi * 8) * VT16_S + lsel * 8) * 2;

    const __half* base = g_qkv16 + (size_t)win * NTOK * QKVN;
    const int hc = head * HD;
    for (int idx = tid; idx < NTOK * 4; idx += 128) {
        int row = idx >> 2, c = idx & 3;
        *reinterpret_cast<uint4*>(&ks[row * KS16_S + c * 8]) =
            *reinterpret_cast<const uint4*>(base + (size_t)row * QKVN + CDIM + hc + c * 8);
        uint4 v4 = *reinterpret_cast<const uint4*>(base + (size_t)row * QKVN + 2 * CDIM + hc + c * 8);
        const __half* hv = reinterpret_cast<const __half*>(&v4);
        #pragma unroll
        for (int j = 0; j < 8; j++)
            vsT[(c * 8 + j) * VT16_S + row] = hv[j];
    }
    __syncthreads();

    const float* bmb = g_bm + (((size_t)L * TWIN + t) * NHEAD + head) * NTOK * NTOK;
    __half* wscr = scr + wid * 16 * SCR16_S;
    const unsigned kbase  = smaddr(ks) + kboff;
    const unsigned pbase  = smaddr(wscr) + paoff;
    const unsigned vbase  = smaddr(vsT) + vboff;
    const unsigned stbase = smaddr(wscr) + (unsigned)((lane & 15) * SCR16_S) * 2;
    const float sc = 0.17677669529663687f;

    for (int mt = wid; mt < 9; mt += 4) {
        const int rb = mt * 16;

        const __half* qA = g_qkv16 + (size_t)(win * NTOK + rb + g) * QKVN + hc;
        const __half* qB = g_qkv16 + (size_t)(win * NTOK + rb + 8 + g) * QKVN + hc;
        unsigned aq[2][4];
        #pragma unroll
        for (int kk2 = 0; kk2 < 2; kk2++) {
            const int kk = kk2 * 16 + 2 * tg;
            aq[kk2][0] = *reinterpret_cast<const unsigned*>(qA + kk);
            aq[kk2][1] = *reinterpret_cast<const unsigned*>(qB + kk);
            aq[kk2][2] = *reinterpret_cast<const unsigned*>(qA + kk + 8);
            aq[kk2][3] = *reinterpret_cast<const unsigned*>(qB + kk + 8);
        }

        float sacc[18][4];
        #pragma unroll
        for (int ntp = 0; ntp < 9; ntp++) {
            float* s0 = sacc[2 * ntp];
            float* s1 = sacc[2 * ntp + 1];
            #pragma unroll
            for (int i = 0; i < 4; i++) { s0[i] = 0.0f; s1[i] = 0.0f; }
            #pragma unroll
            for (int kk2 = 0; kk2 < 2; kk2++) {
                unsigned b0, b1, b2, b3;
                ldsm_x4(b0, b1, b2, b3, kbase + ntp * (16 * KS16_S * 2) + kk2 * 32);
                unsigned bfa[2] = {b0, b1}, bfb[2] = {b2, b3};
                mma_f16(s0, aq[kk2], bfa);
                mma_f16(s1, aq[kk2], bfb);
            }
            #pragma unroll
            for (int h = 0; h < 2; h++) {
                float* sv = h ? s1 : s0;
                const int cb = (2 * ntp + h) * 8;
                const float2 bA = *reinterpret_cast<const float2*>(
                    bmb + (size_t)(rb + g) * NTOK + cb + tg * 2);
                const float2 bB = *reinterpret_cast<const float2*>(
                    bmb + (size_t)(rb + 8 + g) * NTOK + cb + tg * 2);
                sv[0] = fmaf(sv[0], sc, bA.x);
                sv[1] = fmaf(sv[1], sc, bA.y);
                sv[2] = fmaf(sv[2], sc, bB.x);
                sv[3] = fmaf(sv[3], sc, bB.y);
            }
        }

        float mxA = -1e30f, mxB = -1e30f;
        #pragma unroll
        for (int nt = 0; nt < 18; nt++) {
            mxA = fmaxf(mxA, fmaxf(sacc[nt][0], sacc[nt][1]));
            mxB = fmaxf(mxB, fmaxf(sacc[nt][2], sacc[nt][3]));
        }
        #pragma unroll
        for (int o = 1; o <= 2; o <<= 1) {
            mxA = fmaxf(mxA, __shfl_xor_sync(0xFFFFFFFFu, mxA, o));
            mxB = fmaxf(mxB, __shfl_xor_sync(0xFFFFFFFFu, mxB, o));
        }
        float smA = 0.0f, smB = 0.0f;
        #pragma unroll
        for (int nt = 0; nt < 18; nt++) {
            sacc[nt][0] = __expf(sacc[nt][0] - mxA);
            sacc[nt][1] = __expf(sacc[nt][1] - mxA);
            sacc[nt][2] = __expf(sacc[nt][2] - mxB);
            sacc[nt][3] = __expf(sacc[nt][3] - mxB);
            smA += sacc[nt][0] + sacc[nt][1];
            smB += sacc[nt][2] + sacc[nt][3];
        }
        #pragma unroll
        for (int o = 1; o <= 2; o <<= 1) {
            smA += __shfl_xor_sync(0xFFFFFFFFu, smA, o);
            smB += __shfl_xor_sync(0xFFFFFFFFu, smB, o);
        }
        const float invA = 1.0f / smA;
        const float invB = 1.0f / smB;

        #pragma unroll
        for (int nt = 0; nt < 18; nt++) {
            unsigned r0 = h2u(sacc[nt][0], sacc[nt][1]);
            unsigned r1 = h2u(sacc[nt][2], sacc[nt][3]);
            STSM_X2(stbase + nt * 16, r0, r1);
        }
        __syncwarp();

        float oacc[4][4];
        #pragma unroll
        for (int nt = 0; nt < 4; nt++)
            oacc[nt][0] = oacc[nt][1] = oacc[nt][2] = oacc[nt][3] = 0.0f;
        #pragma unroll
        for (int kk = 0; kk < 9; kk++) {
            unsigned ap[4];
            ldsm_x4(ap[0], ap[1], ap[2], ap[3], pbase + kk * 32);
            unsigned b0, b1, b2, b3, c0, c1, c2, c3;
            ldsm_x4(b0, b1, b2, b3, vbase + kk * 32);
            ldsm_x4(c0, c1, c2, c3, vbase + (16 * VT16_S * 2) + kk * 32);
            { unsigned bf[2] = {b0, b1}; mma_f16(oacc[0], ap, bf); }
            { unsigned bf[2] = {b2, b3}; mma_f16(oacc[1], ap, bf); }
            { unsigned bf[2] = {c0, c1}; mma_f16(oacc[2], ap, bf); }
            { unsigned bf[2] = {c2, c3}; mma_f16(oacc[3], ap, bf); }
        }
        __syncwarp();

        #pragma unroll
        for (int nt = 0; nt < 4; nt++) {
            const int c = nt * 8 + tg * 2;
            __half* opA = g_ao16 + ((size_t)win * NTOK + rb + g) * CDIM + hc + c;
            __half* opB = g_ao16 + ((size_t)win * NTOK + rb + 8 + g) * CDIM + hc + c;
            *reinterpret_cast<__half2*>(opA) =
                __floats2half2_rn(oacc[nt][0] * invA, oacc[nt][1] * invA);
            *reinterpret_cast<__half2*>(opB) =
                __floats2half2_rn(oacc[nt][2] * invB, oacc[nt][3] * invB);
        }
    }
}

// ---------------------------------------------------------------------------
// LayerNorm + residual, f16 y input: xout[p] = xin[p] + LN(y[r])*g + b.
// mode 0: p=r; 1: un-window; 2: un-window + un-roll. One warp per row.
// Lane owns channel pairs 2*lane + 64*i (i<3); __half2 / float2 vector I/O.
// ---------------------------------------------------------------------------
__global__ void ln_add_kernel(const __half* __restrict__ y,
                              const float* __restrict__ g,
                              const float* __restrict__ b,
                              const float* __restrict__ xin,
                              float* __restrict__ xout,
                              __half* __restrict__ xh16,
                              int mode) {
    int w = (blockIdx.x * blockDim.x + threadIdx.x) >> 5;
    int lane = threadIdx.x & 31;
    if (w >= MTOK) return;
    size_t p;
    if (mode == 0) {
        p = (size_t)w;
    } else {
        int n = w % NTOK, win = w / NTOK;
        int l = win % NWW, t = win / NWW;
        int tz = t / 8, th = t % 8;
        int z1 = n / 72, h1 = (n % 72) / 12, w1 = n % 12;
        int zr = tz * 2 + z1, hr = th * 6 + h1, wr = l * 12 + w1;
        int z, hh, ww;
        if (mode == 2) { z = (zr + 7) & 7; hh = (hr + 45) % 48; ww = (wr + 186) % 192; }
        else           { z = zr; hh = hr; ww = wr; }
        p = ((size_t)z * 48 + hh) * 192 + ww;
    }
    const __half* yr = y + (size_t)w * CDIM;
    float v[6];
    float sum = 0.0f;
    #pragma unroll
    for (int i = 0; i < 3; i++) {
        const int c = lane * 2 + 64 * i;
        float2 f = __half22float2(*reinterpret_cast<const __half2*>(yr + c));
        v[2 * i] = f.x; v[2 * i + 1] = f.y;
        sum += f.x + f.y;
    }
    #pragma unroll
    for (int o = 16; o; o >>= 1) sum += __shfl_xor_sync(0xFFFFFFFFu, sum, o);
    float mu = sum * (1.0f / 192.0f);
    float var = 0.0f;
    #pragma unroll
    for (int i = 0; i < 6; i++) { float d = v[i] - mu; var += d * d; }
    #pragma unroll
    for (int o = 16; o; o >>= 1) var += __shfl_xor_sync(0xFFFFFFFFu, var, o);
    var *= (1.0f / 192.0f);
    float rs = rsqrtf(var + 1e-5f);
    const float* xi = xin + p * CDIM;
    float* xo = xout + p * CDIM;
    #pragma unroll
    for (int i = 0; i < 3; i++) {
        const int c = lane * 2 + 64 * i;
        const float2 x2 = *reinterpret_cast<const float2*>(xi + c);
        const float2 g2 = *reinterpret_cast<const float2*>(g + c);
        const float2 b2 = *reinterpret_cast<const float2*>(b + c);
        float o0 = x2.x + (v[2 * i]     - mu) * rs * g2.x + b2.x;
        float o1 = x2.y + (v[2 * i + 1] - mu) * rs * g2.y + b2.y;
        *reinterpret_cast<float2*>(xo + c) = make_float2(o0, o1);
        if (xh16)
            *reinterpret_cast<__half2*>(xh16 + p * CDIM + c) = __floats2half2_rn(o0, o1);
    }
}

extern "C" void kernel_launch(void* const* d_in, const int* in_sizes, int n_in,
                              void* d_out, int out_size) {
    const float* x_in       = (const float*)d_in[0];
    const float* qkv_w      = (const float*)d_in[1];
    const float* qkv_b      = (const float*)d_in[2];
    const float* proj_w     = (const float*)d_in[3];
    const float* proj_b     = (const float*)d_in[4];
    const float* bias_table = (const float*)d_in[5];
    const float* n1_g       = (const float*)d_in[6];
    const float* n1_b       = (const float*)d_in[7];
    const float* n2_g       = (const float*)d_in[8];
    const float* n2_b       = (const float*)d_in[9];
    const float* w1         = (const float*)d_in[10];
    const float* b1         = (const float*)d_in[11];
    const float* w2         = (const float*)d_in[12];
    const float* b2         = (const float*)d_in[13];
    // d_in[14..16] = Z,H,W scalars (fixed 8,48,192)

    float  *gx;
    __half *gxh, *gqkv, *gao, *gh, *gwt;
    cudaGetSymbolAddress((void**)&gx,   g_x);
    cudaGetSymbolAddress((void**)&gxh,  g_xh16);
    cudaGetSymbolAddress((void**)&gqkv, g_qkv16);
    cudaGetSymbolAddress((void**)&gao,  g_ao16);
    cudaGetSymbolAddress((void**)&gh,   g_h16);
    cudaGetSymbolAddress((void**)&gwt,  g_wt16);

    cudaFuncSetAttribute(hgemm_kernel<0,1,1>, cudaFuncAttributeMaxDynamicSharedMemorySize, GEMM_SMEM16);
    cudaFuncSetAttribute(hgemm_kernel<0,0,1>, cudaFuncAttributeMaxDynamicSharedMemorySize, GEMM_SMEM16);
    cudaFuncSetAttribute(hgemm_kernel<1,0,1>, cudaFuncAttributeMaxDynamicSharedMemorySize, GEMM_SMEM16);
    cudaFuncSetAttribute(attn_f16_kernel, cudaFuncAttributeMaxDynamicSharedMemorySize, ATTN_SMEM16);

    transpose_all_kernel<<<864, dim3(32, 8)>>>(qkv_w, proj_w, w1, w2);
    cvt_f16_kernel<<<(MTOK * CDIM + 255) / 256, 256>>>(x_in, gxh, MTOK * CDIM);
    {
        size_t total = (size_t)2 * TWIN * NHEAD * NTOK * NTOK;
        biasmask_kernel<<<(unsigned)((total + 255) / 256), 256>>>(bias_table);
    }

    for (int L = 0; L < 2; L++) {
        const float* xsrc = (L == 0) ? x_in : gx;

        // QKV (fused window gather), f16 out -> g_qkv16
        hgemm_kernel<0,1,1><<<dim3(QKVN / 64, MTOK / 128), 256, GEMM_SMEM16>>>(
            gxh, gwt + WQ_OFF + (size_t)L * CDIM * QKVN, qkv_b + (size_t)L * QKVN,
            gqkv, CDIM, QKVN, L);

        attn_f16_kernel<<<dim3(NWIN, NHEAD), 128, ATTN_SMEM16>>>(L);

        // proj: f16 in, f16 out -> g_h16 (free until MLP-up rewrites it)
        hgemm_kernel<0,0,1><<<dim3(CDIM / 64, MTOK / 128), 256, GEMM_SMEM16>>>(
            gao, gwt + WP_OFF + (size_t)L * CDIM * CDIM, proj_b + (size_t)L * CDIM,
            gh, CDIM, CDIM, 0);

        // x = xsrc + LN(un-window(proj_out)); + f16 copy for next GEMM
        ln_add_kernel<<<(MTOK * 32 + 255) / 256, 256>>>(
            gh, n1_g + (size_t)L * CDIM, n1_b + (size_t)L * CDIM,
            xsrc, gx, gxh, L ? 2 : 1);

        // MLP up: gelu, f16 out -> g_h16
        hgemm_kernel<1,0,1><<<dim3(FFN / 64, MTOK / 128), 256, GEMM_SMEM16>>>(
            gxh, gwt + W1_OFF + (size_t)L * CDIM * FFN, b1 + (size_t)L * FFN,
            gh, CDIM, FFN, 0);

        // MLP down: f16 in, f16 out -> g_qkv16 (free; rewritten by next QKV)
        hgemm_kernel<0,0,1><<<dim3(CDIM / 64, MTOK / 128), 256, GEMM_SMEM16>>>(
            gh, gwt + W2_OFF + (size_t)L * FFN * CDIM, b2 + (size_t)L * CDIM,
            gqkv, FFN, CDIM, 0);

        // x = x + LN(mlp_out); final layer writes straight to d_out
        float*  xo  = (L == 1) ? (float*)d_out : gx;
        __half* xho = (L == 1) ? (__half*)nullptr : gxh;
        ln_add_kernel<<<(MTOK * 32 + 255) / 256, 256>>>(
            gqkv, n2_g + (size_t)L * CDIM, n2_b + (size_t)L * CDIM,
            gx, xo, xho, 0);
    }
}